// round 12
// baseline (speedup 1.0000x reference)
#include <cuda_runtime.h>
#include <cuda_bf16.h>
#include <cstdint>

#define B_ 64
#define N_ 512
#define M_ 1024
#define D_ 128

typedef unsigned long long ull;

extern __shared__ char dynsm[];

// ---------------- device scratch (allocation-free) ----------------
__device__ __nv_bfloat16 g_UcHi[(size_t)B_ * N_ * D_];
__device__ __nv_bfloat16 g_UcLo[(size_t)B_ * N_ * D_];
__device__ __nv_bfloat16 g_VpHi[(size_t)B_ * M_ * D_];
__device__ __nv_bfloat16 g_VpLo[(size_t)B_ * M_ * D_];
__device__ uint32_t g_WuH[128 * 64], g_WuL[128 * 64];   // W as u32(bf16x2)
__device__ uint32_t g_WvH[128 * 64], g_WvL[128 * 64];
__device__ float g_ctx[(size_t)1024 * 64 * 128];         // per-tile-half raw ctx
__device__ float g_rs[(size_t)1024 * 64];                // per-tile-half row sums
__device__ float g_part[(size_t)B_ * 8 * D_];

// ---------------- helpers ----------------
__device__ __forceinline__ uint32_t pack_bf16x2(float hi, float lo) {
    uint32_t r;
    asm("cvt.rn.bf16x2.f32 %0, %1, %2;" : "=r"(r) : "f"(hi), "f"(lo));
    return r;
}
__device__ __forceinline__ float lo_f(uint32_t p) { return __uint_as_float(p << 16); }
__device__ __forceinline__ float hi_f(uint32_t p) { return __uint_as_float(p & 0xffff0000u); }

__device__ __forceinline__ uint32_t smem_u32(const void* p) {
    uint32_t a;
    asm("{ .reg .u64 t; cvta.to.shared.u64 t, %1; cvt.u32.u64 %0, t; }"
        : "=r"(a) : "l"(p));
    return a;
}
__device__ __forceinline__ void mma_bf16(float* c, uint32_t a0, uint32_t a1,
                                         uint32_t a2, uint32_t a3,
                                         uint32_t b0, uint32_t b1) {
    asm volatile(
        "mma.sync.aligned.m16n8k16.row.col.f32.bf16.bf16.f32 "
        "{%0,%1,%2,%3},{%4,%5,%6,%7},{%8,%9},{%0,%1,%2,%3};"
        : "+f"(c[0]), "+f"(c[1]), "+f"(c[2]), "+f"(c[3])
        : "r"(a0), "r"(a1), "r"(a2), "r"(a3), "r"(b0), "r"(b1));
}
__device__ __forceinline__ void ldsm_x4(uint32_t& r0, uint32_t& r1, uint32_t& r2,
                                        uint32_t& r3, uint32_t addr) {
    asm volatile("ldmatrix.sync.aligned.m8n8.x4.shared.b16 {%0,%1,%2,%3}, [%4];"
                 : "=r"(r0), "=r"(r1), "=r"(r2), "=r"(r3) : "r"(addr));
}
__device__ __forceinline__ void ldsm_x2(uint32_t& r0, uint32_t& r1, uint32_t addr) {
    asm volatile("ldmatrix.sync.aligned.m8n8.x2.shared.b16 {%0,%1}, [%2];"
                 : "=r"(r0), "=r"(r1) : "r"(addr));
}
__device__ __forceinline__ void ldsm_x2t(uint32_t& r0, uint32_t& r1, uint32_t addr) {
    asm volatile("ldmatrix.sync.aligned.m8n8.x2.trans.shared.b16 {%0,%1}, [%2];"
                 : "=r"(r0), "=r"(r1) : "r"(addr));
}
__device__ __forceinline__ void cpa16(uint32_t dst, const void* src) {
    asm volatile("cp.async.cg.shared.global [%0], [%1], 16;"
                 :: "r"(dst), "l"(src) : "memory");
}
#define CP_COMMIT() asm volatile("cp.async.commit_group;" ::: "memory")
#define CP_WAIT0() asm volatile("cp.async.wait_group 0;" ::: "memory")

// ============================================================================
// One-shot W conversion: fp32 -> bf16 hi/lo, both weight matrices.
// grid 32 x 256: i < 4096 -> U_w, else V_w.
// ============================================================================
__global__ __launch_bounds__(256)
void convw_kernel(const float* __restrict__ Uw, const float* __restrict__ Vw) {
    int i = blockIdx.x * 256 + threadIdx.x;      // 0..8191
    int j = i & 4095;                            // float4 index within matrix
    const float4* src = (i < 4096) ? (const float4*)Uw : (const float4*)Vw;
    uint32_t* dh = (i < 4096) ? g_WuH : g_WvH;
    uint32_t* dl = (i < 4096) ? g_WuL : g_WvL;
    float4 v = src[j];
    uint32_t h0 = pack_bf16x2(v.y, v.x);
    uint32_t l0 = pack_bf16x2(v.y - hi_f(h0), v.x - lo_f(h0));
    uint32_t h1 = pack_bf16x2(v.w, v.z);
    uint32_t l1 = pack_bf16x2(v.w - hi_f(h1), v.z - lo_f(h1));
    dh[j * 2] = h0; dh[j * 2 + 1] = h1;
    dl[j * 2] = l0; dl[j * 2 + 1] = l1;
}

// ============================================================================
// Projection via HMMA: relu(X @ W^T + b) -> bf16 hi/lo. W pre-converted.
// ============================================================================
#define PJ_WH 0
#define PJ_WL 34816
#define PJ_XH 69632
#define PJ_XL 87040
#define PROJ_SMEM 104448

__global__ __launch_bounds__(512, 1)
void proj_kernel(const float* __restrict__ X,
                 const uint32_t* __restrict__ WHg,
                 const uint32_t* __restrict__ WLg,
                 const float* __restrict__ bias,
                 __nv_bfloat16* __restrict__ outHi,
                 __nv_bfloat16* __restrict__ outLo) {
    char* sm = dynsm;
    const uint32_t smu = smem_u32(sm);
    const int tid = threadIdx.x, wid = tid >> 5, lane = tid & 31;
    const int wr = wid & 3, wc = wid >> 2;
    const int g = lane >> 2, t = lane & 3;
    const size_t row0 = (size_t)blockIdx.x * 64;

    // stage pre-converted W (128 rows x 16 uint4 each buffer)
    uint4* WHs = (uint4*)(sm + PJ_WH);
    uint4* WLs = (uint4*)(sm + PJ_WL);
    const uint4* WHg4 = (const uint4*)WHg;
    const uint4* WLg4 = (const uint4*)WLg;
    #pragma unroll
    for (int it = 0; it < 4; it++) {
        int i = it * 512 + tid;                  // 2048 uint4
        int r = i >> 4, c = i & 15;
        WHs[r * 17 + c] = WHg4[i];
        WLs[r * 17 + c] = WLg4[i];
    }
    // stage X tile (64x128 fp32 -> hi/lo)
    uint32_t* XH = (uint32_t*)(sm + PJ_XH);
    uint32_t* XL = (uint32_t*)(sm + PJ_XL);
    const float4* Xg = (const float4*)(X + row0 * D_);
    #pragma unroll
    for (int it = 0; it < 4; it++) {
        int i = it * 512 + tid;                  // 2048 float4
        int r = i >> 5, c4 = i & 31;
        float4 v = Xg[i];
        uint32_t h0 = pack_bf16x2(v.y, v.x);
        uint32_t l0 = pack_bf16x2(v.y - hi_f(h0), v.x - lo_f(h0));
        uint32_t h1 = pack_bf16x2(v.w, v.z);
        uint32_t l1 = pack_bf16x2(v.w - hi_f(h1), v.z - lo_f(h1));
        XH[r * 68 + c4 * 2] = h0; XH[r * 68 + c4 * 2 + 1] = h1;
        XL[r * 68 + c4 * 2] = l0; XL[r * 68 + c4 * 2 + 1] = l1;
    }
    __syncthreads();

    const int l7 = lane & 7, l8 = (lane >> 3) & 1, l16 = lane >> 4;
    const uint32_t aoffH = smu + PJ_XH + ((16 * wr + l7 + l8 * 8) * 68 + l16 * 4) * 4;
    const uint32_t aoffL = smu + PJ_XL + ((16 * wr + l7 + l8 * 8) * 68 + l16 * 4) * 4;
    const uint32_t boffH = smu + PJ_WH + ((wc * 32 + l7) * 68 + l8 * 4) * 4;
    const uint32_t boffL = smu + PJ_WL + ((wc * 32 + l7) * 68 + l8 * 4) * 4;

    float accA[4][4], accB[4][4];
    #pragma unroll
    for (int j = 0; j < 4; j++)
        #pragma unroll
        for (int q = 0; q < 4; q++) { accA[j][q] = 0.0f; accB[j][q] = 0.0f; }

    #pragma unroll
    for (int kk = 0; kk < 8; kk++) {
        uint32_t ah0, ah1, ah2, ah3, al0, al1, al2, al3;
        ldsm_x4(ah0, ah1, ah2, ah3, aoffH + kk * 32);
        ldsm_x4(al0, al1, al2, al3, aoffL + kk * 32);
        #pragma unroll
        for (int j = 0; j < 4; j++) {
            uint32_t bh0, bh1, bl0, bl1;
            ldsm_x2(bh0, bh1, boffH + j * 2176 + kk * 32);
            ldsm_x2(bl0, bl1, boffL + j * 2176 + kk * 32);
            mma_bf16(accA[j], ah0, ah1, ah2, ah3, bh0, bh1);
            mma_bf16(accB[j], ah0, ah1, ah2, ah3, bl0, bl1);
            mma_bf16(accB[j], al0, al1, al2, al3, bh0, bh1);
        }
    }

    const int rA = 16 * wr + g;
    const float2* b2 = (const float2*)bias;
    uint32_t* oH = (uint32_t*)outHi;
    uint32_t* oL = (uint32_t*)outLo;
    #pragma unroll
    for (int j = 0; j < 4; j++) {
        const int cpair = wc * 16 + j * 4 + t;
        float2 bb = b2[cpair];
        float o0 = fmaxf(accA[j][0] + accB[j][0] + bb.x, 0.0f);
        float o1 = fmaxf(accA[j][1] + accB[j][1] + bb.y, 0.0f);
        uint32_t h = pack_bf16x2(o1, o0);
        uint32_t l = pack_bf16x2(o1 - hi_f(h), o0 - lo_f(h));
        oH[(row0 + rA) * 64 + cpair] = h;
        oL[(row0 + rA) * 64 + cpair] = l;
        float o2 = fmaxf(accA[j][2] + accB[j][2] + bb.x, 0.0f);
        float o3 = fmaxf(accA[j][3] + accB[j][3] + bb.y, 0.0f);
        uint32_t h2 = pack_bf16x2(o3, o2);
        uint32_t l2 = pack_bf16x2(o3 - hi_f(h2), o2 - lo_f(h2));
        oH[(row0 + rA + 8) * 64 + cpair] = h2;
        oL[(row0 + rA + 8) * 64 + cpair] = l2;
    }
}

// ============================================================================
// Fused attention, split-m: CTA = (b, nt, mh). 1024 CTAs, 512 thr,
// warp grid 4(n) x 4(m-slice). 8 m-chunks of 64 per CTA (its half of M).
// Register-resident P; raw ctx + rowsums dumped to global (fixed-shift
// softmax => partials additive). finalize_kernel merges halves.
// ============================================================================
#define OFF_UCH 0
#define OFF_UCL 17408
#define OFF_VH0 34816
#define OFF_VL0 52224
#define OFF_VH1 69632
#define OFF_VL1 87040
#define OFF_RS  104448
#define ATTN_SMEM 107776

__global__ __launch_bounds__(512, 1)
void attn_kernel(float* __restrict__ ctx_out, float* __restrict__ rs_out) {
    char* sm = dynsm;
    const uint32_t smu = smem_u32(sm);
    const int tid = threadIdx.x, wid = tid >> 5, lane = tid & 31;
    const int wr = wid & 3, wc = wid >> 2;          // 4 x 4 warp grid
    const int g = lane >> 2, t = lane & 3;
    const int b = blockIdx.x >> 4;
    const int nt = (blockIdx.x >> 1) & 7;
    const int mh = blockIdx.x & 1;

    uint32_t* UC32h = (uint32_t*)(sm + OFF_UCH);   // stride 68 u32 per row
    uint32_t* UC32l = (uint32_t*)(sm + OFF_UCL);
    float* RS = (float*)(sm + OFF_RS);

    const uint4* ucHg = (const uint4*)(g_UcHi + ((size_t)(b * N_ + nt * 64)) * D_);
    const uint4* ucLg = (const uint4*)(g_UcLo + ((size_t)(b * N_ + nt * 64)) * D_);
    const uint4* vpHg = (const uint4*)(g_VpHi + (size_t)b * M_ * D_) + (size_t)mh * 512 * 16;
    const uint4* vpLg = (const uint4*)(g_VpLo + (size_t)b * M_ * D_) + (size_t)mh * 512 * 16;

    // stage Uc
    uint4* UH4 = (uint4*)(sm + OFF_UCH);
    uint4* UL4 = (uint4*)(sm + OFF_UCL);
    #pragma unroll
    for (int it = 0; it < 2; it++) {
        int i = it * 512 + tid;
        int r = i >> 4, c = i & 15;
        UH4[r * 17 + c] = ucHg[i];
        UL4[r * 17 + c] = ucLg[i];
    }

    const uint32_t vhB[2] = {smu + OFF_VH0, smu + OFF_VH1};
    const uint32_t vlB[2] = {smu + OFF_VL0, smu + OFF_VL1};

    const int l7 = lane & 7, l8 = (lane >> 3) & 1, l16 = lane >> 4;
    const uint32_t aoffH = smu + OFF_UCH + ((16 * wr + l7 + l8 * 8) * 68 + l16 * 4) * 4;
    const uint32_t aoffL = smu + OFF_UCL + ((16 * wr + l7 + l8 * 8) * 68 + l16 * 4) * 4;
    const uint32_t boffV = ((wc * 16 + l7) * 68 + l8 * 4) * 4;
    const uint32_t boffT = ((wc * 16 + l8 * 8 + l7) * 68) * 4;

    const int rA = 16 * wr + g;
    float cacc[16][4];
    #pragma unroll
    for (int j = 0; j < 16; j++)
        #pragma unroll
        for (int q = 0; q < 4; q++) cacc[j][q] = 0.0f;
    float rs0 = 0.0f, rs1 = 0.0f;

    // stage chunk 0
    #pragma unroll
    for (int it = 0; it < 2; it++) {
        int i = it * 512 + tid;
        int r = i >> 4, c = i & 15;
        cpa16(vhB[0] + (r * 68 + c * 4) * 4, vpHg + r * 16 + c);
        cpa16(vlB[0] + (r * 68 + c * 4) * 4, vpLg + r * 16 + c);
    }
    CP_COMMIT();

    for (int mc = 0; mc < 8; mc++) {
        const int s = mc & 1;
        CP_WAIT0();
        __syncthreads();
        if (mc + 1 < 8) {
            const int s2 = s ^ 1;
            #pragma unroll
            for (int it = 0; it < 2; it++) {
                int i = it * 512 + tid;
                int r = i >> 4, c = i & 15;
                cpa16(vhB[s2] + (r * 68 + c * 4) * 4,
                      vpHg + ((mc + 1) * 64 + r) * 16 + c);
                cpa16(vlB[s2] + (r * 68 + c * 4) * 4,
                      vpLg + ((mc + 1) * 64 + r) * 16 + c);
            }
            CP_COMMIT();
        }

        // ---- scores: 16n x 16m (own m-slice), k=128 ----
        float accA[2][4], accB[2][4];
        #pragma unroll
        for (int j = 0; j < 2; j++)
            #pragma unroll
            for (int q = 0; q < 4; q++) { accA[j][q] = 0.0f; accB[j][q] = 0.0f; }

        const uint32_t bvh = vhB[s] + boffV, bvl = vlB[s] + boffV;
        #pragma unroll
        for (int kk = 0; kk < 8; kk++) {
            uint32_t ah0, ah1, ah2, ah3, al0, al1, al2, al3;
            ldsm_x4(ah0, ah1, ah2, ah3, aoffH + kk * 32);
            ldsm_x4(al0, al1, al2, al3, aoffL + kk * 32);
            #pragma unroll
            for (int j = 0; j < 2; j++) {
                uint32_t bh0, bh1, bl0, bl1;
                ldsm_x2(bh0, bh1, bvh + j * 2176 + kk * 32);
                ldsm_x2(bl0, bl1, bvl + j * 2176 + kk * 32);
                mma_bf16(accA[j], ah0, ah1, ah2, ah3, bh0, bh1);
                mma_bf16(accB[j], ah0, ah1, ah2, ah3, bl0, bl1);
                mma_bf16(accB[j], al0, al1, al2, al3, bh0, bh1);
            }
        }

        // ---- exp in registers; C-frags -> ctx A-frags ----
        float e0 = __expf(accA[0][0] + accB[0][0] - 40.0f);
        float e1 = __expf(accA[0][1] + accB[0][1] - 40.0f);
        float e2 = __expf(accA[0][2] + accB[0][2] - 40.0f);
        float e3 = __expf(accA[0][3] + accB[0][3] - 40.0f);
        float f0 = __expf(accA[1][0] + accB[1][0] - 40.0f);
        float f1 = __expf(accA[1][1] + accB[1][1] - 40.0f);
        float f2 = __expf(accA[1][2] + accB[1][2] - 40.0f);
        float f3 = __expf(accA[1][3] + accB[1][3] - 40.0f);
        rs0 += e0 + e1 + f0 + f1;
        rs1 += e2 + e3 + f2 + f3;
        uint32_t ph0 = pack_bf16x2(e1, e0);
        uint32_t ph1 = pack_bf16x2(e3, e2);
        uint32_t ph2 = pack_bf16x2(f1, f0);
        uint32_t ph3 = pack_bf16x2(f3, f2);
        uint32_t pl0 = pack_bf16x2(e1 - hi_f(ph0), e0 - lo_f(ph0));
        uint32_t pl1 = pack_bf16x2(e3 - hi_f(ph1), e2 - lo_f(ph1));
        uint32_t pl2 = pack_bf16x2(f1 - hi_f(ph2), f0 - lo_f(ph2));
        uint32_t pl3 = pack_bf16x2(f3 - hi_f(ph3), f2 - lo_f(ph3));

        // ---- ctx partial: 16n x 128d, k=16 (own m-slice) ----
        const uint32_t bth = vhB[s] + boffT, btl = vlB[s] + boffT;
        #pragma unroll
        for (int j = 0; j < 16; j++) {
            uint32_t bh0, bh1, bl0, bl1;
            ldsm_x2t(bh0, bh1, bth + j * 16);
            ldsm_x2t(bl0, bl1, btl + j * 16);
            mma_bf16(cacc[j], ph0, ph1, ph2, ph3, bh0, bh1);
            mma_bf16(cacc[j], pl0, pl1, pl2, pl3, bh0, bh1);
            mma_bf16(cacc[j], ph0, ph1, ph2, ph3, bl0, bl1);
        }
    }

    // ---- row sums (partial over this m-half) ----
    rs0 += __shfl_xor_sync(0xffffffffu, rs0, 1);
    rs0 += __shfl_xor_sync(0xffffffffu, rs0, 2);
    rs1 += __shfl_xor_sync(0xffffffffu, rs1, 1);
    rs1 += __shfl_xor_sync(0xffffffffu, rs1, 2);
    if (t == 0) {
        RS[wc * 64 + rA] = rs0;
        RS[wc * 64 + rA + 8] = rs1;
    }
    __syncthreads();
    if (tid < 64)
        rs_out[(size_t)blockIdx.x * 64 + tid] =
            RS[tid] + RS[64 + tid] + RS[128 + tid] + RS[192 + tid];

    // ---- merge cacc over wc into Jt (raw ctx) ----
    float* Jt = (float*)(sm + OFF_VH0);   // 64 x 132 f32 (reuses V area)
    #pragma unroll
    for (int p = 0; p < 4; p++) {
        if (wc == p) {
            #pragma unroll
            for (int j = 0; j < 16; j++) {
                const int d0 = j * 8 + 2 * t;
                if (p == 0) {
                    Jt[rA * 132 + d0]           = cacc[j][0];
                    Jt[rA * 132 + d0 + 1]       = cacc[j][1];
                    Jt[(rA + 8) * 132 + d0]     = cacc[j][2];
                    Jt[(rA + 8) * 132 + d0 + 1] = cacc[j][3];
                } else {
                    Jt[rA * 132 + d0]           += cacc[j][0];
                    Jt[rA * 132 + d0 + 1]       += cacc[j][1];
                    Jt[(rA + 8) * 132 + d0]     += cacc[j][2];
                    Jt[(rA + 8) * 132 + d0 + 1] += cacc[j][3];
                }
            }
        }
        __syncthreads();
    }

    // ---- dump raw ctx (64 x 128) to global ----
    float4* gctx4 = (float4*)(ctx_out + (size_t)blockIdx.x * 8192);
    #pragma unroll
    for (int it = 0; it < 4; it++) {
        int i = it * 512 + tid;               // 2048 float4
        int row = i >> 5, c4 = i & 31;
        gctx4[i] = *(float4*)&Jt[row * 132 + c4 * 4];
    }
}

// ============================================================================
// Finalize: merge the two m-halves, normalize, add Uc, n-reduce per tile.
// grid 512 = (b, nt), 256 thr.
// ============================================================================
__global__ __launch_bounds__(256)
void finalize_kernel(const float* __restrict__ ctx, const float* __restrict__ rs,
                     float* __restrict__ part) {
    __shared__ float INVs[64];
    __shared__ float RED[256];
    const int x = blockIdx.x;
    const int b = x >> 3, nt = x & 7;
    const int tid = threadIdx.x;

    if (tid < 64)
        INVs[tid] = 1.0f / (rs[(size_t)(2 * x) * 64 + tid] +
                            rs[(size_t)(2 * x + 1) * 64 + tid]);
    __syncthreads();

    const int h = tid >> 7, d = tid & 127;
    const uint32_t* ucH = (const uint32_t*)g_UcHi + (size_t)(b * N_ + nt * 64) * 64;
    const uint32_t* ucL = (const uint32_t*)g_UcLo + (size_t)(b * N_ + nt * 64) * 64;
    const float* c0 = ctx + (size_t)(2 * x) * 8192;
    const float* c1 = ctx + (size_t)(2 * x + 1) * 8192;

    float s = 0.0f;
    #pragma unroll
    for (int r = 0; r < 32; r++) {
        int row = h * 32 + r;
        float cv = c0[row * 128 + d] + c1[row * 128 + d];
        uint32_t uh = ucH[row * 64 + (d >> 1)];
        uint32_t ul = ucL[row * 64 + (d >> 1)];
        float uc = (d & 1) ? (hi_f(uh) + hi_f(ul)) : (lo_f(uh) + lo_f(ul));
        s += uc + cv * INVs[row];
    }
    RED[tid] = s;
    __syncthreads();
    if (tid < 128)
        part[(size_t)x * D_ + tid] = RED[tid] + RED[128 + tid];
}

// ============================================================================
__global__ __launch_bounds__(256)
void reduce_kernel(const float* __restrict__ part, const float* __restrict__ q,
                   float* __restrict__ out) {
    int i = blockIdx.x * blockDim.x + threadIdx.x;
    int b = i >> 7, d = i & 127;
    float s = 0.0f;
    #pragma unroll
    for (int nt = 0; nt < 8; nt++)
        s += part[(size_t)(b * 8 + nt) * D_ + d];
    out[i] = s * q[d] * (1.0f / (float)N_);
}

// ============================================================================
extern "C" void kernel_launch(void* const* d_in, const int* in_sizes, int n_in,
                              void* d_out, int out_size) {
    const float* h_c = (const float*)d_in[0];
    const float* h_p = (const float*)d_in[1];
    const float* U_w = (const float*)d_in[2];
    const float* U_b = (const float*)d_in[3];
    const float* V_w = (const float*)d_in[4];
    const float* V_b = (const float*)d_in[5];
    const float* q   = (const float*)d_in[6];
    float* out = (float*)d_out;

    void *pUcH, *pUcL, *pVpH, *pVpL, *pWuH, *pWuL, *pWvH, *pWvL;
    void *pCtx, *pRs, *pPart;
    cudaGetSymbolAddress(&pUcH, g_UcHi);
    cudaGetSymbolAddress(&pUcL, g_UcLo);
    cudaGetSymbolAddress(&pVpH, g_VpHi);
    cudaGetSymbolAddress(&pVpL, g_VpLo);
    cudaGetSymbolAddress(&pWuH, g_WuH);
    cudaGetSymbolAddress(&pWuL, g_WuL);
    cudaGetSymbolAddress(&pWvH, g_WvH);
    cudaGetSymbolAddress(&pWvL, g_WvL);
    cudaGetSymbolAddress(&pCtx, g_ctx);
    cudaGetSymbolAddress(&pRs, g_rs);
    cudaGetSymbolAddress(&pPart, g_part);

    cudaFuncSetAttribute(proj_kernel,
                         cudaFuncAttributeMaxDynamicSharedMemorySize, PROJ_SMEM);
    cudaFuncSetAttribute(attn_kernel,
                         cudaFuncAttributeMaxDynamicSharedMemorySize, ATTN_SMEM);

    convw_kernel<<<32, 256>>>(U_w, V_w);
    proj_kernel<<<(B_ * N_) / 64, 512, PROJ_SMEM>>>(
        h_c, (const uint32_t*)pWuH, (const uint32_t*)pWuL, U_b,
        (__nv_bfloat16*)pUcH, (__nv_bfloat16*)pUcL);
    proj_kernel<<<(B_ * M_) / 64, 512, PROJ_SMEM>>>(
        h_p, (const uint32_t*)pWvH, (const uint32_t*)pWvL, V_b,
        (__nv_bfloat16*)pVpH, (__nv_bfloat16*)pVpL);
    attn_kernel<<<B_ * 16, 512, ATTN_SMEM>>>((float*)pCtx, (float*)pRs);
    finalize_kernel<<<B_ * 8, 256>>>((const float*)pCtx, (const float*)pRs,
                                     (float*)pPart);
    reduce_kernel<<<(B_ * D_) / 256, 256>>>((const float*)pPart, q, out);
}

// round 13
// speedup vs baseline: 1.0754x; 1.0754x over previous
#include <cuda_runtime.h>
#include <cuda_bf16.h>
#include <cstdint>

#define B_ 64
#define N_ 512
#define M_ 1024
#define D_ 128

typedef unsigned long long ull;

extern __shared__ char dynsm[];

// ---------------- device scratch (allocation-free) ----------------
__device__ __nv_bfloat16 g_UcHi[(size_t)B_ * N_ * D_];
__device__ __nv_bfloat16 g_UcLo[(size_t)B_ * N_ * D_];
__device__ __nv_bfloat16 g_VpHi[(size_t)B_ * M_ * D_];
__device__ __nv_bfloat16 g_VpLo[(size_t)B_ * M_ * D_];
__device__ uint32_t g_WuH[128 * 64], g_WuL[128 * 64];   // W as u32(bf16x2)
__device__ uint32_t g_WvH[128 * 64], g_WvL[128 * 64];
__device__ float g_part[(size_t)B_ * 16 * D_];

// ---------------- helpers ----------------
__device__ __forceinline__ uint32_t pack_bf16x2(float hi, float lo) {
    uint32_t r;
    asm("cvt.rn.bf16x2.f32 %0, %1, %2;" : "=r"(r) : "f"(hi), "f"(lo));
    return r;
}
__device__ __forceinline__ float lo_f(uint32_t p) { return __uint_as_float(p << 16); }
__device__ __forceinline__ float hi_f(uint32_t p) { return __uint_as_float(p & 0xffff0000u); }

__device__ __forceinline__ uint32_t smem_u32(const void* p) {
    uint32_t a;
    asm("{ .reg .u64 t; cvta.to.shared.u64 t, %1; cvt.u32.u64 %0, t; }"
        : "=r"(a) : "l"(p));
    return a;
}
__device__ __forceinline__ void mma_bf16(float* c, uint32_t a0, uint32_t a1,
                                         uint32_t a2, uint32_t a3,
                                         uint32_t b0, uint32_t b1) {
    asm volatile(
        "mma.sync.aligned.m16n8k16.row.col.f32.bf16.bf16.f32 "
        "{%0,%1,%2,%3},{%4,%5,%6,%7},{%8,%9},{%0,%1,%2,%3};"
        : "+f"(c[0]), "+f"(c[1]), "+f"(c[2]), "+f"(c[3])
        : "r"(a0), "r"(a1), "r"(a2), "r"(a3), "r"(b0), "r"(b1));
}
__device__ __forceinline__ void ldsm_x4(uint32_t& r0, uint32_t& r1, uint32_t& r2,
                                        uint32_t& r3, uint32_t addr) {
    asm volatile("ldmatrix.sync.aligned.m8n8.x4.shared.b16 {%0,%1,%2,%3}, [%4];"
                 : "=r"(r0), "=r"(r1), "=r"(r2), "=r"(r3) : "r"(addr));
}
__device__ __forceinline__ void ldsm_x2(uint32_t& r0, uint32_t& r1, uint32_t addr) {
    asm volatile("ldmatrix.sync.aligned.m8n8.x2.shared.b16 {%0,%1}, [%2];"
                 : "=r"(r0), "=r"(r1) : "r"(addr));
}
__device__ __forceinline__ void ldsm_x2t(uint32_t& r0, uint32_t& r1, uint32_t addr) {
    asm volatile("ldmatrix.sync.aligned.m8n8.x2.trans.shared.b16 {%0,%1}, [%2];"
                 : "=r"(r0), "=r"(r1) : "r"(addr));
}
__device__ __forceinline__ void cpa16(uint32_t dst, const void* src) {
    asm volatile("cp.async.cg.shared.global [%0], [%1], 16;"
                 :: "r"(dst), "l"(src) : "memory");
}
#define CP_COMMIT() asm volatile("cp.async.commit_group;" ::: "memory")
#define CP_WAIT0() asm volatile("cp.async.wait_group 0;" ::: "memory")

// ============================================================================
// One-shot W conversion: fp32 -> bf16 hi/lo, both weight matrices.
// ============================================================================
__global__ __launch_bounds__(256)
void convw_kernel(const float* __restrict__ Uw, const float* __restrict__ Vw) {
    int i = blockIdx.x * 256 + threadIdx.x;      // 0..8191
    int j = i & 4095;
    const float4* src = (i < 4096) ? (const float4*)Uw : (const float4*)Vw;
    uint32_t* dh = (i < 4096) ? g_WuH : g_WvH;
    uint32_t* dl = (i < 4096) ? g_WuL : g_WvL;
    float4 v = src[j];
    uint32_t h0 = pack_bf16x2(v.y, v.x);
    uint32_t l0 = pack_bf16x2(v.y - hi_f(h0), v.x - lo_f(h0));
    uint32_t h1 = pack_bf16x2(v.w, v.z);
    uint32_t l1 = pack_bf16x2(v.w - hi_f(h1), v.z - lo_f(h1));
    dh[j * 2] = h0; dh[j * 2 + 1] = h1;
    dl[j * 2] = l0; dl[j * 2 + 1] = l1;
}

// ============================================================================
// Projection via HMMA: relu(X @ W^T + b) -> bf16 hi/lo. W pre-converted.
// ============================================================================
#define PJ_WH 0
#define PJ_WL 34816
#define PJ_XH 69632
#define PJ_XL 87040
#define PROJ_SMEM 104448

__global__ __launch_bounds__(512, 1)
void proj_kernel(const float* __restrict__ X,
                 const uint32_t* __restrict__ WHg,
                 const uint32_t* __restrict__ WLg,
                 const float* __restrict__ bias,
                 __nv_bfloat16* __restrict__ outHi,
                 __nv_bfloat16* __restrict__ outLo) {
    char* sm = dynsm;
    const uint32_t smu = smem_u32(sm);
    const int tid = threadIdx.x, wid = tid >> 5, lane = tid & 31;
    const int wr = wid & 3, wc = wid >> 2;
    const int g = lane >> 2, t = lane & 3;
    const size_t row0 = (size_t)blockIdx.x * 64;

    uint4* WHs = (uint4*)(sm + PJ_WH);
    uint4* WLs = (uint4*)(sm + PJ_WL);
    const uint4* WHg4 = (const uint4*)WHg;
    const uint4* WLg4 = (const uint4*)WLg;
    #pragma unroll
    for (int it = 0; it < 4; it++) {
        int i = it * 512 + tid;
        int r = i >> 4, c = i & 15;
        WHs[r * 17 + c] = WHg4[i];
        WLs[r * 17 + c] = WLg4[i];
    }
    uint32_t* XH = (uint32_t*)(sm + PJ_XH);
    uint32_t* XL = (uint32_t*)(sm + PJ_XL);
    const float4* Xg = (const float4*)(X + row0 * D_);
    #pragma unroll
    for (int it = 0; it < 4; it++) {
        int i = it * 512 + tid;
        int r = i >> 5, c4 = i & 31;
        float4 v = Xg[i];
        uint32_t h0 = pack_bf16x2(v.y, v.x);
        uint32_t l0 = pack_bf16x2(v.y - hi_f(h0), v.x - lo_f(h0));
        uint32_t h1 = pack_bf16x2(v.w, v.z);
        uint32_t l1 = pack_bf16x2(v.w - hi_f(h1), v.z - lo_f(h1));
        XH[r * 68 + c4 * 2] = h0; XH[r * 68 + c4 * 2 + 1] = h1;
        XL[r * 68 + c4 * 2] = l0; XL[r * 68 + c4 * 2 + 1] = l1;
    }
    __syncthreads();

    const int l7 = lane & 7, l8 = (lane >> 3) & 1, l16 = lane >> 4;
    const uint32_t aoffH = smu + PJ_XH + ((16 * wr + l7 + l8 * 8) * 68 + l16 * 4) * 4;
    const uint32_t aoffL = smu + PJ_XL + ((16 * wr + l7 + l8 * 8) * 68 + l16 * 4) * 4;
    const uint32_t boffH = smu + PJ_WH + ((wc * 32 + l7) * 68 + l8 * 4) * 4;
    const uint32_t boffL = smu + PJ_WL + ((wc * 32 + l7) * 68 + l8 * 4) * 4;

    float accA[4][4], accB[4][4];
    #pragma unroll
    for (int j = 0; j < 4; j++)
        #pragma unroll
        for (int q = 0; q < 4; q++) { accA[j][q] = 0.0f; accB[j][q] = 0.0f; }

    #pragma unroll
    for (int kk = 0; kk < 8; kk++) {
        uint32_t ah0, ah1, ah2, ah3, al0, al1, al2, al3;
        ldsm_x4(ah0, ah1, ah2, ah3, aoffH + kk * 32);
        ldsm_x4(al0, al1, al2, al3, aoffL + kk * 32);
        #pragma unroll
        for (int j = 0; j < 4; j++) {
            uint32_t bh0, bh1, bl0, bl1;
            ldsm_x2(bh0, bh1, boffH + j * 2176 + kk * 32);
            ldsm_x2(bl0, bl1, boffL + j * 2176 + kk * 32);
            mma_bf16(accA[j], ah0, ah1, ah2, ah3, bh0, bh1);
            mma_bf16(accB[j], ah0, ah1, ah2, ah3, bl0, bl1);
            mma_bf16(accB[j], al0, al1, al2, al3, bh0, bh1);
        }
    }

    const int rA = 16 * wr + g;
    const float2* b2 = (const float2*)bias;
    uint32_t* oH = (uint32_t*)outHi;
    uint32_t* oL = (uint32_t*)outLo;
    #pragma unroll
    for (int j = 0; j < 4; j++) {
        const int cpair = wc * 16 + j * 4 + t;
        float2 bb = b2[cpair];
        float o0 = fmaxf(accA[j][0] + accB[j][0] + bb.x, 0.0f);
        float o1 = fmaxf(accA[j][1] + accB[j][1] + bb.y, 0.0f);
        uint32_t h = pack_bf16x2(o1, o0);
        uint32_t l = pack_bf16x2(o1 - hi_f(h), o0 - lo_f(h));
        oH[(row0 + rA) * 64 + cpair] = h;
        oL[(row0 + rA) * 64 + cpair] = l;
        float o2 = fmaxf(accA[j][2] + accB[j][2] + bb.x, 0.0f);
        float o3 = fmaxf(accA[j][3] + accB[j][3] + bb.y, 0.0f);
        uint32_t h2 = pack_bf16x2(o3, o2);
        uint32_t l2 = pack_bf16x2(o3 - hi_f(h2), o2 - lo_f(h2));
        oH[(row0 + rA + 8) * 64 + cpair] = h2;
        oL[(row0 + rA + 8) * 64 + cpair] = l2;
    }
}

// ============================================================================
// Fused attention, n-split: CTA = (b, 32-row n-tile). Grid 1024, 256 thr,
// 2 CTAs/SM. Warp grid 2(n: wr) x 4(m-slice: wc). 16 m-chunks of 64.
// Register-resident P (same per-warp inner loop as before). Softmax fully
// local to the CTA -> no merge kernel.
// ============================================================================
#define OFF_UCH 0
#define OFF_UCL 8704
#define OFF_VH0 17408
#define OFF_VL0 34816
#define OFF_VH1 52224
#define OFF_VL1 69632
#define OFF_RS  87040
#define OFF_INV 87552
#define OFF_RED 87680
#define ATTN_SMEM 88704

__global__ __launch_bounds__(256, 2)
void attn_kernel(float* __restrict__ part) {
    char* sm = dynsm;
    const uint32_t smu = smem_u32(sm);
    const int tid = threadIdx.x, wid = tid >> 5, lane = tid & 31;
    const int wr = wid & 1, wc = wid >> 1;          // 2 x 4 warp grid
    const int g = lane >> 2, t = lane & 3;
    const int b = blockIdx.x >> 4, nt = blockIdx.x & 15;

    uint32_t* UC32h = (uint32_t*)(sm + OFF_UCH);   // 32 rows, stride 68 u32
    uint32_t* UC32l = (uint32_t*)(sm + OFF_UCL);
    float* RS  = (float*)(sm + OFF_RS);
    float* INV = (float*)(sm + OFF_INV);
    float* RED = (float*)(sm + OFF_RED);

    const uint4* ucHg = (const uint4*)(g_UcHi + ((size_t)(b * N_ + nt * 32)) * D_);
    const uint4* ucLg = (const uint4*)(g_UcLo + ((size_t)(b * N_ + nt * 32)) * D_);
    const uint4* vpHg = (const uint4*)(g_VpHi + (size_t)b * M_ * D_);
    const uint4* vpLg = (const uint4*)(g_VpLo + (size_t)b * M_ * D_);

    // stage Uc (32 rows x 16 uint4 per buffer)
    uint4* UH4 = (uint4*)(sm + OFF_UCH);
    uint4* UL4 = (uint4*)(sm + OFF_UCL);
    #pragma unroll
    for (int it = 0; it < 2; it++) {
        int i = it * 256 + tid;
        int r = i >> 4, c = i & 15;
        UH4[r * 17 + c] = ucHg[i];
        UL4[r * 17 + c] = ucLg[i];
    }

    const uint32_t vhB[2] = {smu + OFF_VH0, smu + OFF_VH1};
    const uint32_t vlB[2] = {smu + OFF_VL0, smu + OFF_VL1};

    const int l7 = lane & 7, l8 = (lane >> 3) & 1, l16 = lane >> 4;
    const uint32_t aoffH = smu + OFF_UCH + ((16 * wr + l7 + l8 * 8) * 68 + l16 * 4) * 4;
    const uint32_t aoffL = smu + OFF_UCL + ((16 * wr + l7 + l8 * 8) * 68 + l16 * 4) * 4;
    const uint32_t boffV = ((wc * 16 + l7) * 68 + l8 * 4) * 4;
    const uint32_t boffT = ((wc * 16 + l8 * 8 + l7) * 68) * 4;

    const int rA = 16 * wr + g;
    float cacc[16][4];
    #pragma unroll
    for (int j = 0; j < 16; j++)
        #pragma unroll
        for (int q = 0; q < 4; q++) cacc[j][q] = 0.0f;
    float rs0 = 0.0f, rs1 = 0.0f;

    // stage chunk 0 (64 rows x 16 uint4, hi+lo = 2048 cpa16 / 256 thr)
    #pragma unroll
    for (int it = 0; it < 4; it++) {
        int i = it * 256 + tid;
        int r = i >> 4, c = i & 15;
        cpa16(vhB[0] + (r * 68 + c * 4) * 4, vpHg + r * 16 + c);
        cpa16(vlB[0] + (r * 68 + c * 4) * 4, vpLg + r * 16 + c);
    }
    CP_COMMIT();

    for (int mc = 0; mc < 16; mc++) {
        const int s = mc & 1;
        CP_WAIT0();
        __syncthreads();
        if (mc + 1 < 16) {
            const int s2 = s ^ 1;
            #pragma unroll
            for (int it = 0; it < 4; it++) {
                int i = it * 256 + tid;
                int r = i >> 4, c = i & 15;
                cpa16(vhB[s2] + (r * 68 + c * 4) * 4,
                      vpHg + ((mc + 1) * 64 + r) * 16 + c);
                cpa16(vlB[s2] + (r * 68 + c * 4) * 4,
                      vpLg + ((mc + 1) * 64 + r) * 16 + c);
            }
            CP_COMMIT();
        }

        // ---- scores: 16n x 16m (own m-slice), k=128 ----
        float accA[2][4], accB[2][4];
        #pragma unroll
        for (int j = 0; j < 2; j++)
            #pragma unroll
            for (int q = 0; q < 4; q++) { accA[j][q] = 0.0f; accB[j][q] = 0.0f; }

        const uint32_t bvh = vhB[s] + boffV, bvl = vlB[s] + boffV;
        #pragma unroll
        for (int kk = 0; kk < 8; kk++) {
            uint32_t ah0, ah1, ah2, ah3, al0, al1, al2, al3;
            ldsm_x4(ah0, ah1, ah2, ah3, aoffH + kk * 32);
            ldsm_x4(al0, al1, al2, al3, aoffL + kk * 32);
            #pragma unroll
            for (int j = 0; j < 2; j++) {
                uint32_t bh0, bh1, bl0, bl1;
                ldsm_x2(bh0, bh1, bvh + j * 2176 + kk * 32);
                ldsm_x2(bl0, bl1, bvl + j * 2176 + kk * 32);
                mma_bf16(accA[j], ah0, ah1, ah2, ah3, bh0, bh1);
                mma_bf16(accB[j], ah0, ah1, ah2, ah3, bl0, bl1);
                mma_bf16(accB[j], al0, al1, al2, al3, bh0, bh1);
            }
        }

        // ---- exp in registers; C-frags -> ctx A-frags ----
        float e0 = __expf(accA[0][0] + accB[0][0] - 40.0f);
        float e1 = __expf(accA[0][1] + accB[0][1] - 40.0f);
        float e2 = __expf(accA[0][2] + accB[0][2] - 40.0f);
        float e3 = __expf(accA[0][3] + accB[0][3] - 40.0f);
        float f0 = __expf(accA[1][0] + accB[1][0] - 40.0f);
        float f1 = __expf(accA[1][1] + accB[1][1] - 40.0f);
        float f2 = __expf(accA[1][2] + accB[1][2] - 40.0f);
        float f3 = __expf(accA[1][3] + accB[1][3] - 40.0f);
        rs0 += e0 + e1 + f0 + f1;
        rs1 += e2 + e3 + f2 + f3;
        uint32_t ph0 = pack_bf16x2(e1, e0);
        uint32_t ph1 = pack_bf16x2(e3, e2);
        uint32_t ph2 = pack_bf16x2(f1, f0);
        uint32_t ph3 = pack_bf16x2(f3, f2);
        uint32_t pl0 = pack_bf16x2(e1 - hi_f(ph0), e0 - lo_f(ph0));
        uint32_t pl1 = pack_bf16x2(e3 - hi_f(ph1), e2 - lo_f(ph1));
        uint32_t pl2 = pack_bf16x2(f1 - hi_f(ph2), f0 - lo_f(ph2));
        uint32_t pl3 = pack_bf16x2(f3 - hi_f(ph3), f2 - lo_f(ph3));

        // ---- ctx partial: 16n x 128d, k=16 (own m-slice) ----
        const uint32_t bth = vhB[s] + boffT, btl = vlB[s] + boffT;
        #pragma unroll
        for (int j = 0; j < 16; j++) {
            uint32_t bh0, bh1, bl0, bl1;
            ldsm_x2t(bh0, bh1, bth + j * 16);
            ldsm_x2t(bl0, bl1, btl + j * 16);
            mma_bf16(cacc[j], ph0, ph1, ph2, ph3, bh0, bh1);
            mma_bf16(cacc[j], pl0, pl1, pl2, pl3, bh0, bh1);
            mma_bf16(cacc[j], ph0, ph1, ph2, ph3, bl0, bl1);
        }
    }

    // ---- row sums -> inverse (4 wc m-slices per row) ----
    rs0 += __shfl_xor_sync(0xffffffffu, rs0, 1);
    rs0 += __shfl_xor_sync(0xffffffffu, rs0, 2);
    rs1 += __shfl_xor_sync(0xffffffffu, rs1, 1);
    rs1 += __shfl_xor_sync(0xffffffffu, rs1, 2);
    if (t == 0) {
        RS[wc * 32 + rA] = rs0;
        RS[wc * 32 + rA + 8] = rs1;
    }
    __syncthreads();
    if (tid < 32)
        INV[tid] = 1.0f / (RS[tid] + RS[32 + tid] + RS[64 + tid] + RS[96 + tid]);
    __syncthreads();

    // ---- sum ctx partials over wc into Jt (raw, unnormalized) ----
    float* Jt = (float*)(sm + OFF_VH0);   // 32 x 132 f32 (reuses V area)
    #pragma unroll
    for (int p = 0; p < 4; p++) {
        if (wc == p) {
            #pragma unroll
            for (int j = 0; j < 16; j++) {
                const int d0 = j * 8 + 2 * t;
                if (p == 0) {
                    Jt[rA * 132 + d0]           = cacc[j][0];
                    Jt[rA * 132 + d0 + 1]       = cacc[j][1];
                    Jt[(rA + 8) * 132 + d0]     = cacc[j][2];
                    Jt[(rA + 8) * 132 + d0 + 1] = cacc[j][3];
                } else {
                    Jt[rA * 132 + d0]           += cacc[j][0];
                    Jt[rA * 132 + d0 + 1]       += cacc[j][1];
                    Jt[(rA + 8) * 132 + d0]     += cacc[j][2];
                    Jt[(rA + 8) * 132 + d0 + 1] += cacc[j][3];
                }
            }
        }
        __syncthreads();
    }

    // ---- n-reduce: sum over rows of (Uc + ctx*inv) ----
    {
        int h = tid >> 7, d = tid & 127;   // 2 groups x 16 rows
        float s = 0.0f;
        #pragma unroll
        for (int r = 0; r < 16; r++) {
            int row = h * 16 + r;
            uint32_t uh = UC32h[row * 68 + (d >> 1)];
            uint32_t ul = UC32l[row * 68 + (d >> 1)];
            float uc = (d & 1) ? (hi_f(uh) + hi_f(ul)) : (lo_f(uh) + lo_f(ul));
            s += uc + Jt[row * 132 + d] * INV[row];
        }
        RED[h * 128 + d] = s;
    }
    __syncthreads();
    if (tid < 128)
        part[(size_t)blockIdx.x * D_ + tid] = RED[tid] + RED[128 + tid];
}

// ============================================================================
__global__ __launch_bounds__(256)
void reduce_kernel(const float* __restrict__ part, const float* __restrict__ q,
                   float* __restrict__ out) {
    int i = blockIdx.x * blockDim.x + threadIdx.x;
    int b = i >> 7, d = i & 127;
    float s = 0.0f;
    #pragma unroll
    for (int nt = 0; nt < 16; nt++)
        s += part[(size_t)(b * 16 + nt) * D_ + d];
    out[i] = s * q[d] * (1.0f / (float)N_);
}

// ============================================================================
extern "C" void kernel_launch(void* const* d_in, const int* in_sizes, int n_in,
                              void* d_out, int out_size) {
    const float* h_c = (const float*)d_in[0];
    const float* h_p = (const float*)d_in[1];
    const float* U_w = (const float*)d_in[2];
    const float* U_b = (const float*)d_in[3];
    const float* V_w = (const float*)d_in[4];
    const float* V_b = (const float*)d_in[5];
    const float* q   = (const float*)d_in[6];
    float* out = (float*)d_out;

    void *pUcH, *pUcL, *pVpH, *pVpL, *pWuH, *pWuL, *pWvH, *pWvL, *pPart;
    cudaGetSymbolAddress(&pUcH, g_UcHi);
    cudaGetSymbolAddress(&pUcL, g_UcLo);
    cudaGetSymbolAddress(&pVpH, g_VpHi);
    cudaGetSymbolAddress(&pVpL, g_VpLo);
    cudaGetSymbolAddress(&pWuH, g_WuH);
    cudaGetSymbolAddress(&pWuL, g_WuL);
    cudaGetSymbolAddress(&pWvH, g_WvH);
    cudaGetSymbolAddress(&pWvL, g_WvL);
    cudaGetSymbolAddress(&pPart, g_part);

    cudaFuncSetAttribute(proj_kernel,
                         cudaFuncAttributeMaxDynamicSharedMemorySize, PROJ_SMEM);
    cudaFuncSetAttribute(attn_kernel,
                         cudaFuncAttributeMaxDynamicSharedMemorySize, ATTN_SMEM);

    convw_kernel<<<32, 256>>>(U_w, V_w);
    proj_kernel<<<(B_ * N_) / 64, 512, PROJ_SMEM>>>(
        h_c, (const uint32_t*)pWuH, (const uint32_t*)pWuL, U_b,
        (__nv_bfloat16*)pUcH, (__nv_bfloat16*)pUcL);
    proj_kernel<<<(B_ * M_) / 64, 512, PROJ_SMEM>>>(
        h_p, (const uint32_t*)pWvH, (const uint32_t*)pWvL, V_b,
        (__nv_bfloat16*)pVpH, (__nv_bfloat16*)pVpL);
    attn_kernel<<<B_ * 16, 256, ATTN_SMEM>>>((float*)pPart);
    reduce_kernel<<<(B_ * D_) / 256, 256>>>((const float*)pPart, q, out);
}

// round 14
// speedup vs baseline: 1.2414x; 1.1544x over previous
#include <cuda_runtime.h>
#include <cuda_bf16.h>
#include <cstdint>

#define B_ 64
#define N_ 512
#define M_ 1024
#define D_ 128

typedef unsigned long long ull;

extern __shared__ char dynsm[];

// ---------------- device scratch (allocation-free) ----------------
// (Uc/Vp buffers hold fp16 hi/lo halves; declared as raw 2-byte storage)
__device__ __nv_bfloat16 g_UcHi[(size_t)B_ * N_ * D_];
__device__ __nv_bfloat16 g_UcLo[(size_t)B_ * N_ * D_];
__device__ __nv_bfloat16 g_VpHi[(size_t)B_ * M_ * D_];
__device__ __nv_bfloat16 g_VpLo[(size_t)B_ * M_ * D_];
__device__ uint32_t g_WuH[128 * 64], g_WuL[128 * 64];   // W as u32(bf16x2)
__device__ uint32_t g_WvH[128 * 64], g_WvL[128 * 64];
__device__ float g_part[(size_t)B_ * 16 * D_];

// ---------------- helpers ----------------
__device__ __forceinline__ uint32_t pack_bf16x2(float hi, float lo) {
    uint32_t r;
    asm("cvt.rn.bf16x2.f32 %0, %1, %2;" : "=r"(r) : "f"(hi), "f"(lo));
    return r;
}
__device__ __forceinline__ float lo_f(uint32_t p) { return __uint_as_float(p << 16); }
__device__ __forceinline__ float hi_f(uint32_t p) { return __uint_as_float(p & 0xffff0000u); }

__device__ __forceinline__ uint32_t pack_f16x2(float hi, float lo) {
    uint32_t r;
    asm("cvt.rn.f16x2.f32 %0, %1, %2;" : "=r"(r) : "f"(hi), "f"(lo));
    return r;
}
__device__ __forceinline__ float f16lo(uint32_t p) {
    float f;
    asm("{.reg .b16 l, h; mov.b32 {l, h}, %1; cvt.f32.f16 %0, l;}"
        : "=f"(f) : "r"(p));
    return f;
}
__device__ __forceinline__ float f16hi(uint32_t p) {
    float f;
    asm("{.reg .b16 l, h; mov.b32 {l, h}, %1; cvt.f32.f16 %0, h;}"
        : "=f"(f) : "r"(p));
    return f;
}

__device__ __forceinline__ uint32_t smem_u32(const void* p) {
    uint32_t a;
    asm("{ .reg .u64 t; cvta.to.shared.u64 t, %1; cvt.u32.u64 %0, t; }"
        : "=r"(a) : "l"(p));
    return a;
}
__device__ __forceinline__ void mma_bf16(float* c, uint32_t a0, uint32_t a1,
                                         uint32_t a2, uint32_t a3,
                                         uint32_t b0, uint32_t b1) {
    asm volatile(
        "mma.sync.aligned.m16n8k16.row.col.f32.bf16.bf16.f32 "
        "{%0,%1,%2,%3},{%4,%5,%6,%7},{%8,%9},{%0,%1,%2,%3};"
        : "+f"(c[0]), "+f"(c[1]), "+f"(c[2]), "+f"(c[3])
        : "r"(a0), "r"(a1), "r"(a2), "r"(a3), "r"(b0), "r"(b1));
}
__device__ __forceinline__ void mma_f16(float* c, uint32_t a0, uint32_t a1,
                                        uint32_t a2, uint32_t a3,
                                        uint32_t b0, uint32_t b1) {
    asm volatile(
        "mma.sync.aligned.m16n8k16.row.col.f32.f16.f16.f32 "
        "{%0,%1,%2,%3},{%4,%5,%6,%7},{%8,%9},{%0,%1,%2,%3};"
        : "+f"(c[0]), "+f"(c[1]), "+f"(c[2]), "+f"(c[3])
        : "r"(a0), "r"(a1), "r"(a2), "r"(a3), "r"(b0), "r"(b1));
}
__device__ __forceinline__ void ldsm_x4(uint32_t& r0, uint32_t& r1, uint32_t& r2,
                                        uint32_t& r3, uint32_t addr) {
    asm volatile("ldmatrix.sync.aligned.m8n8.x4.shared.b16 {%0,%1,%2,%3}, [%4];"
                 : "=r"(r0), "=r"(r1), "=r"(r2), "=r"(r3) : "r"(addr));
}
__device__ __forceinline__ void ldsm_x2(uint32_t& r0, uint32_t& r1, uint32_t addr) {
    asm volatile("ldmatrix.sync.aligned.m8n8.x2.shared.b16 {%0,%1}, [%2];"
                 : "=r"(r0), "=r"(r1) : "r"(addr));
}
__device__ __forceinline__ void ldsm_x4t(uint32_t& r0, uint32_t& r1, uint32_t& r2,
                                         uint32_t& r3, uint32_t addr) {
    asm volatile("ldmatrix.sync.aligned.m8n8.x4.trans.shared.b16 {%0,%1,%2,%3}, [%4];"
                 : "=r"(r0), "=r"(r1), "=r"(r2), "=r"(r3) : "r"(addr));
}
__device__ __forceinline__ void cpa16(uint32_t dst, const void* src) {
    asm volatile("cp.async.cg.shared.global [%0], [%1], 16;"
                 :: "r"(dst), "l"(src) : "memory");
}
#define CP_COMMIT() asm volatile("cp.async.commit_group;" ::: "memory")
#define CP_WAIT0() asm volatile("cp.async.wait_group 0;" ::: "memory")

// ============================================================================
// One-shot W conversion: fp32 -> bf16 hi/lo (for proj's internal bf16 MMA).
// ============================================================================
__global__ __launch_bounds__(256)
void convw_kernel(const float* __restrict__ Uw, const float* __restrict__ Vw) {
    int i = blockIdx.x * 256 + threadIdx.x;      // 0..8191
    int j = i & 4095;
    const float4* src = (i < 4096) ? (const float4*)Uw : (const float4*)Vw;
    uint32_t* dh = (i < 4096) ? g_WuH : g_WvH;
    uint32_t* dl = (i < 4096) ? g_WuL : g_WvL;
    float4 v = src[j];
    uint32_t h0 = pack_bf16x2(v.y, v.x);
    uint32_t l0 = pack_bf16x2(v.y - hi_f(h0), v.x - lo_f(h0));
    uint32_t h1 = pack_bf16x2(v.w, v.z);
    uint32_t l1 = pack_bf16x2(v.w - hi_f(h1), v.z - lo_f(h1));
    dh[j * 2] = h0; dh[j * 2 + 1] = h1;
    dl[j * 2] = l0; dl[j * 2 + 1] = l1;
}

// ============================================================================
// Projection via bf16 HMMA: relu(X @ W^T + b) -> fp16 hi/lo outputs.
// ============================================================================
#define PJ_WH 0
#define PJ_WL 34816
#define PJ_XH 69632
#define PJ_XL 87040
#define PROJ_SMEM 104448

__global__ __launch_bounds__(512, 1)
void proj_kernel(const float* __restrict__ X,
                 const uint32_t* __restrict__ WHg,
                 const uint32_t* __restrict__ WLg,
                 const float* __restrict__ bias,
                 __nv_bfloat16* __restrict__ outHi,
                 __nv_bfloat16* __restrict__ outLo) {
    char* sm = dynsm;
    const uint32_t smu = smem_u32(sm);
    const int tid = threadIdx.x, wid = tid >> 5, lane = tid & 31;
    const int wr = wid & 3, wc = wid >> 2;
    const int g = lane >> 2, t = lane & 3;
    const size_t row0 = (size_t)blockIdx.x * 64;

    uint4* WHs = (uint4*)(sm + PJ_WH);
    uint4* WLs = (uint4*)(sm + PJ_WL);
    const uint4* WHg4 = (const uint4*)WHg;
    const uint4* WLg4 = (const uint4*)WLg;
    #pragma unroll
    for (int it = 0; it < 4; it++) {
        int i = it * 512 + tid;
        int r = i >> 4, c = i & 15;
        WHs[r * 17 + c] = WHg4[i];
        WLs[r * 17 + c] = WLg4[i];
    }
    uint32_t* XH = (uint32_t*)(sm + PJ_XH);
    uint32_t* XL = (uint32_t*)(sm + PJ_XL);
    const float4* Xg = (const float4*)(X + row0 * D_);
    #pragma unroll
    for (int it = 0; it < 4; it++) {
        int i = it * 512 + tid;
        int r = i >> 5, c4 = i & 31;
        float4 v = Xg[i];
        uint32_t h0 = pack_bf16x2(v.y, v.x);
        uint32_t l0 = pack_bf16x2(v.y - hi_f(h0), v.x - lo_f(h0));
        uint32_t h1 = pack_bf16x2(v.w, v.z);
        uint32_t l1 = pack_bf16x2(v.w - hi_f(h1), v.z - lo_f(h1));
        XH[r * 68 + c4 * 2] = h0; XH[r * 68 + c4 * 2 + 1] = h1;
        XL[r * 68 + c4 * 2] = l0; XL[r * 68 + c4 * 2 + 1] = l1;
    }
    __syncthreads();

    const int l7 = lane & 7, l8 = (lane >> 3) & 1, l16 = lane >> 4;
    const uint32_t aoffH = smu + PJ_XH + ((16 * wr + l7 + l8 * 8) * 68 + l16 * 4) * 4;
    const uint32_t aoffL = smu + PJ_XL + ((16 * wr + l7 + l8 * 8) * 68 + l16 * 4) * 4;
    const uint32_t boffH = smu + PJ_WH + ((wc * 32 + l7) * 68 + l8 * 4) * 4;
    const uint32_t boffL = smu + PJ_WL + ((wc * 32 + l7) * 68 + l8 * 4) * 4;

    float accA[4][4], accB[4][4];
    #pragma unroll
    for (int j = 0; j < 4; j++)
        #pragma unroll
        for (int q = 0; q < 4; q++) { accA[j][q] = 0.0f; accB[j][q] = 0.0f; }

    #pragma unroll
    for (int kk = 0; kk < 8; kk++) {
        uint32_t ah0, ah1, ah2, ah3, al0, al1, al2, al3;
        ldsm_x4(ah0, ah1, ah2, ah3, aoffH + kk * 32);
        ldsm_x4(al0, al1, al2, al3, aoffL + kk * 32);
        #pragma unroll
        for (int j = 0; j < 4; j++) {
            uint32_t bh0, bh1, bl0, bl1;
            ldsm_x2(bh0, bh1, boffH + j * 2176 + kk * 32);
            ldsm_x2(bl0, bl1, boffL + j * 2176 + kk * 32);
            mma_bf16(accA[j], ah0, ah1, ah2, ah3, bh0, bh1);
            mma_bf16(accB[j], ah0, ah1, ah2, ah3, bl0, bl1);
            mma_bf16(accB[j], al0, al1, al2, al3, bh0, bh1);
        }
    }

    // epilogue: bias + relu + fp16 hi/lo split
    const int rA = 16 * wr + g;
    const float2* b2 = (const float2*)bias;
    uint32_t* oH = (uint32_t*)outHi;
    uint32_t* oL = (uint32_t*)outLo;
    #pragma unroll
    for (int j = 0; j < 4; j++) {
        const int cpair = wc * 16 + j * 4 + t;
        float2 bb = b2[cpair];
        float o0 = fmaxf(accA[j][0] + accB[j][0] + bb.x, 0.0f);
        float o1 = fmaxf(accA[j][1] + accB[j][1] + bb.y, 0.0f);
        uint32_t h = pack_f16x2(o1, o0);
        uint32_t l = pack_f16x2(o1 - f16hi(h), o0 - f16lo(h));
        oH[(row0 + rA) * 64 + cpair] = h;
        oL[(row0 + rA) * 64 + cpair] = l;
        float o2 = fmaxf(accA[j][2] + accB[j][2] + bb.x, 0.0f);
        float o3 = fmaxf(accA[j][3] + accB[j][3] + bb.y, 0.0f);
        uint32_t h2 = pack_f16x2(o3, o2);
        uint32_t l2 = pack_f16x2(o3 - f16hi(h2), o2 - f16lo(h2));
        oH[(row0 + rA + 8) * 64 + cpair] = h2;
        oL[(row0 + rA + 8) * 64 + cpair] = l2;
    }
}

// ============================================================================
// Fused attention, fp16 + per-warp online max:
// CTA = (b, 32-row n-tile), grid 1024, 256 thr, 2 CTAs/SM.
// Warp grid 2(n) x 4(m-slice). Scores: 3-term fp16 split. Ctx: SINGLE
// fp16 MMA (P_f16 x Vh_f16), k=16 per chunk, per-warp local max frame.
// ============================================================================
#define OFF_UCH 0
#define OFF_UCL 8704
#define OFF_VH0 17408
#define OFF_VL0 34816
#define OFF_VH1 52224
#define OFF_VL1 69632
#define OFF_MX  87040
#define OFF_RSS 87552
#define OFF_MXR 88064
#define OFF_INV 88192
#define OFF_RED 88320
#define ATTN_SMEM 89344

__global__ __launch_bounds__(256, 2)
void attn_kernel(float* __restrict__ part) {
    char* sm = dynsm;
    const uint32_t smu = smem_u32(sm);
    const int tid = threadIdx.x, wid = tid >> 5, lane = tid & 31;
    const int wr = wid & 1, wc = wid >> 1;          // 2 x 4 warp grid
    const int g = lane >> 2, t = lane & 3;
    const int b = blockIdx.x >> 4, nt = blockIdx.x & 15;

    uint32_t* UC32h = (uint32_t*)(sm + OFF_UCH);   // 32 rows, stride 68 u32
    uint32_t* UC32l = (uint32_t*)(sm + OFF_UCL);
    float* MXs = (float*)(sm + OFF_MX);
    float* RSs = (float*)(sm + OFF_RSS);
    float* MXR = (float*)(sm + OFF_MXR);
    float* INV = (float*)(sm + OFF_INV);
    float* RED = (float*)(sm + OFF_RED);

    const uint4* ucHg = (const uint4*)(g_UcHi + ((size_t)(b * N_ + nt * 32)) * D_);
    const uint4* ucLg = (const uint4*)(g_UcLo + ((size_t)(b * N_ + nt * 32)) * D_);
    const uint4* vpHg = (const uint4*)(g_VpHi + (size_t)b * M_ * D_);
    const uint4* vpLg = (const uint4*)(g_VpLo + (size_t)b * M_ * D_);

    // stage Uc (32 rows x 16 uint4 per buffer)
    uint4* UH4 = (uint4*)(sm + OFF_UCH);
    uint4* UL4 = (uint4*)(sm + OFF_UCL);
    #pragma unroll
    for (int it = 0; it < 2; it++) {
        int i = it * 256 + tid;
        int r = i >> 4, c = i & 15;
        UH4[r * 17 + c] = ucHg[i];
        UL4[r * 17 + c] = ucLg[i];
    }

    const uint32_t vhB[2] = {smu + OFF_VH0, smu + OFF_VH1};
    const uint32_t vlB[2] = {smu + OFF_VL0, smu + OFF_VL1};

    const int l7 = lane & 7, l8 = (lane >> 3) & 1, l16 = lane >> 4;
    const uint32_t aoffH = smu + OFF_UCH + ((16 * wr + l7 + l8 * 8) * 68 + l16 * 4) * 4;
    const uint32_t aoffL = smu + OFF_UCL + ((16 * wr + l7 + l8 * 8) * 68 + l16 * 4) * 4;
    // scores B x4: lanes 0-15 -> j=0 (k halves via l8), 16-31 -> j=1
    const uint32_t boffV4 = ((wc * 16 + l16 * 8 + l7) * 68 + l8 * 4) * 4;
    // ctx B x4 trans: lanes 0-15 -> d-tile j (k halves via l8), 16-31 -> j+1
    const uint32_t boffT4 = ((wc * 16 + l8 * 8 + l7) * 68) * 4 + l16 * 16;

    const int rA = 16 * wr + g;
    float cacc[16][4];
    #pragma unroll
    for (int j = 0; j < 16; j++)
        #pragma unroll
        for (int q = 0; q < 4; q++) cacc[j][q] = 0.0f;
    float rs0 = 0.0f, rs1 = 0.0f;
    float mx0 = 0.0f, mx1 = 0.0f;     // scores >= 0 (ReLU operands)

    // stage chunk 0
    #pragma unroll
    for (int it = 0; it < 4; it++) {
        int i = it * 256 + tid;
        int r = i >> 4, c = i & 15;
        cpa16(vhB[0] + (r * 68 + c * 4) * 4, vpHg + r * 16 + c);
        cpa16(vlB[0] + (r * 68 + c * 4) * 4, vpLg + r * 16 + c);
    }
    CP_COMMIT();

    for (int mc = 0; mc < 16; mc++) {
        const int s = mc & 1;
        CP_WAIT0();
        __syncthreads();
        if (mc + 1 < 16) {
            const int s2 = s ^ 1;
            #pragma unroll
            for (int it = 0; it < 4; it++) {
                int i = it * 256 + tid;
                int r = i >> 4, c = i & 15;
                cpa16(vhB[s2] + (r * 68 + c * 4) * 4,
                      vpHg + ((mc + 1) * 64 + r) * 16 + c);
                cpa16(vlB[s2] + (r * 68 + c * 4) * 4,
                      vpLg + ((mc + 1) * 64 + r) * 16 + c);
            }
            CP_COMMIT();
        }

        // ---- scores: 16n x 16m (own m-slice), k=128, fp16 3-term ----
        float accA[2][4], accB[2][4];
        #pragma unroll
        for (int j = 0; j < 2; j++)
            #pragma unroll
            for (int q = 0; q < 4; q++) { accA[j][q] = 0.0f; accB[j][q] = 0.0f; }

        const uint32_t bvh = vhB[s] + boffV4, bvl = vlB[s] + boffV4;
        #pragma unroll
        for (int kk = 0; kk < 8; kk++) {
            uint32_t ah0, ah1, ah2, ah3, al0, al1, al2, al3;
            ldsm_x4(ah0, ah1, ah2, ah3, aoffH + kk * 32);
            ldsm_x4(al0, al1, al2, al3, aoffL + kk * 32);
            uint32_t bh0, bh1, bh2, bh3, bl0, bl1, bl2, bl3;
            ldsm_x4(bh0, bh1, bh2, bh3, bvh + kk * 32);
            ldsm_x4(bl0, bl1, bl2, bl3, bvl + kk * 32);
            mma_f16(accA[0], ah0, ah1, ah2, ah3, bh0, bh1);
            mma_f16(accB[0], ah0, ah1, ah2, ah3, bl0, bl1);
            mma_f16(accB[0], al0, al1, al2, al3, bh0, bh1);
            mma_f16(accA[1], ah0, ah1, ah2, ah3, bh2, bh3);
            mma_f16(accB[1], ah0, ah1, ah2, ah3, bl2, bl3);
            mma_f16(accB[1], al0, al1, al2, al3, bh2, bh3);
        }

        // ---- per-warp online max + exp + fp16 P pack ----
        float s00 = accA[0][0] + accB[0][0], s01 = accA[0][1] + accB[0][1];
        float s02 = accA[0][2] + accB[0][2], s03 = accA[0][3] + accB[0][3];
        float s10 = accA[1][0] + accB[1][0], s11 = accA[1][1] + accB[1][1];
        float s12 = accA[1][2] + accB[1][2], s13 = accA[1][3] + accB[1][3];
        float c0 = fmaxf(fmaxf(s00, s01), fmaxf(s10, s11));
        float c1 = fmaxf(fmaxf(s02, s03), fmaxf(s12, s13));
        c0 = fmaxf(c0, __shfl_xor_sync(0xffffffffu, c0, 1));
        c0 = fmaxf(c0, __shfl_xor_sync(0xffffffffu, c0, 2));
        c1 = fmaxf(c1, __shfl_xor_sync(0xffffffffu, c1, 1));
        c1 = fmaxf(c1, __shfl_xor_sync(0xffffffffu, c1, 2));
        float nm0 = fmaxf(mx0, c0), nm1 = fmaxf(mx1, c1);
        float scl0 = __expf(mx0 - nm0), scl1 = __expf(mx1 - nm1);
        mx0 = nm0; mx1 = nm1;
        float e0 = __expf(s00 - nm0), e1 = __expf(s01 - nm0);
        float f0 = __expf(s10 - nm0), f1 = __expf(s11 - nm0);
        float e2 = __expf(s02 - nm1), e3 = __expf(s03 - nm1);
        float f2 = __expf(s12 - nm1), f3 = __expf(s13 - nm1);
        rs0 = rs0 * scl0 + (e0 + e1 + f0 + f1);
        rs1 = rs1 * scl1 + (e2 + e3 + f2 + f3);
        uint32_t ph0 = pack_f16x2(e1, e0);
        uint32_t ph1 = pack_f16x2(e3, e2);
        uint32_t ph2 = pack_f16x2(f1, f0);
        uint32_t ph3 = pack_f16x2(f3, f2);
        #pragma unroll
        for (int j = 0; j < 16; j++) {
            cacc[j][0] *= scl0; cacc[j][1] *= scl0;
            cacc[j][2] *= scl1; cacc[j][3] *= scl1;
        }

        // ---- ctx partial: 16n x 128d, k=16, SINGLE-term fp16 ----
        const uint32_t bth = vhB[s] + boffT4;
        #pragma unroll
        for (int j = 0; j < 16; j += 2) {
            uint32_t b0, b1, b2, b3;
            ldsm_x4t(b0, b1, b2, b3, bth + j * 16);
            mma_f16(cacc[j],     ph0, ph1, ph2, ph3, b0, b1);
            mma_f16(cacc[j + 1], ph0, ph1, ph2, ph3, b2, b3);
        }
    }

    // ---- per-warp (mx, rs) -> smem; merge frames across wc ----
    rs0 += __shfl_xor_sync(0xffffffffu, rs0, 1);
    rs0 += __shfl_xor_sync(0xffffffffu, rs0, 2);
    rs1 += __shfl_xor_sync(0xffffffffu, rs1, 1);
    rs1 += __shfl_xor_sync(0xffffffffu, rs1, 2);
    if (t == 0) {
        MXs[wc * 32 + rA] = mx0;  MXs[wc * 32 + rA + 8] = mx1;
        RSs[wc * 32 + rA] = rs0;  RSs[wc * 32 + rA + 8] = rs1;
    }
    __syncthreads();
    if (tid < 32) {
        float m0 = MXs[tid], m1 = MXs[32 + tid];
        float m2 = MXs[64 + tid], m3 = MXs[96 + tid];
        float M = fmaxf(fmaxf(m0, m1), fmaxf(m2, m3));
        float R = RSs[tid] * __expf(m0 - M) + RSs[32 + tid] * __expf(m1 - M) +
                  RSs[64 + tid] * __expf(m2 - M) + RSs[96 + tid] * __expf(m3 - M);
        MXR[tid] = M;
        INV[tid] = 1.0f / R;
    }
    __syncthreads();

    const float sc0 = __expf(mx0 - MXR[rA]);
    const float sc1 = __expf(mx1 - MXR[rA + 8]);

    // ---- sum scaled ctx partials over wc into Jt ----
    float* Jt = (float*)(sm + OFF_VH0);   // 32 x 132 f32 (reuses V area)
    #pragma unroll
    for (int p = 0; p < 4; p++) {
        if (wc == p) {
            #pragma unroll
            for (int j = 0; j < 16; j++) {
                const int d0 = j * 8 + 2 * t;
                if (p == 0) {
                    Jt[rA * 132 + d0]           = cacc[j][0] * sc0;
                    Jt[rA * 132 + d0 + 1]       = cacc[j][1] * sc0;
                    Jt[(rA + 8) * 132 + d0]     = cacc[j][2] * sc1;
                    Jt[(rA + 8) * 132 + d0 + 1] = cacc[j][3] * sc1;
                } else {
                    Jt[rA * 132 + d0]           += cacc[j][0] * sc0;
                    Jt[rA * 132 + d0 + 1]       += cacc[j][1] * sc0;
                    Jt[(rA + 8) * 132 + d0]     += cacc[j][2] * sc1;
                    Jt[(rA + 8) * 132 + d0 + 1] += cacc[j][3] * sc1;
                }
            }
        }
        __syncthreads();
    }

    // ---- n-reduce: sum over rows of (Uc + ctx*inv) ----
    {
        int h = tid >> 7, d = tid & 127;   // 2 groups x 16 rows
        float s = 0.0f;
        #pragma unroll
        for (int r = 0; r < 16; r++) {
            int row = h * 16 + r;
            uint32_t uh = UC32h[row * 68 + (d >> 1)];
            uint32_t ul = UC32l[row * 68 + (d >> 1)];
            float uc = (d & 1) ? (f16hi(uh) + f16hi(ul)) : (f16lo(uh) + f16lo(ul));
            s += uc + Jt[row * 132 + d] * INV[row];
        }
        RED[h * 128 + d] = s;
    }
    __syncthreads();
    if (tid < 128)
        part[(size_t)blockIdx.x * D_ + tid] = RED[tid] + RED[128 + tid];
}

// ============================================================================
__global__ __launch_bounds__(256)
void reduce_kernel(const float* __restrict__ part, const float* __restrict__ q,
                   float* __restrict__ out) {
    int i = blockIdx.x * blockDim.x + threadIdx.x;
    int b = i >> 7, d = i & 127;
    float s = 0.0f;
    #pragma unroll
    for (int nt = 0; nt < 16; nt++)
        s += part[(size_t)(b * 16 + nt) * D_ + d];
    out[i] = s * q[d] * (1.0f / (float)N_);
}

// ============================================================================
extern "C" void kernel_launch(void* const* d_in, const int* in_sizes, int n_in,
                              void* d_out, int out_size) {
    const float* h_c = (const float*)d_in[0];
    const float* h_p = (const float*)d_in[1];
    const float* U_w = (const float*)d_in[2];
    const float* U_b = (const float*)d_in[3];
    const float* V_w = (const float*)d_in[4];
    const float* V_b = (const float*)d_in[5];
    const float* q   = (const float*)d_in[6];
    float* out = (float*)d_out;

    void *pUcH, *pUcL, *pVpH, *pVpL, *pWuH, *pWuL, *pWvH, *pWvL, *pPart;
    cudaGetSymbolAddress(&pUcH, g_UcHi);
    cudaGetSymbolAddress(&pUcL, g_UcLo);
    cudaGetSymbolAddress(&pVpH, g_VpHi);
    cudaGetSymbolAddress(&pVpL, g_VpLo);
    cudaGetSymbolAddress(&pWuH, g_WuH);
    cudaGetSymbolAddress(&pWuL, g_WuL);
    cudaGetSymbolAddress(&pWvH, g_WvH);
    cudaGetSymbolAddress(&pWvL, g_WvL);
    cudaGetSymbolAddress(&pPart, g_part);

    cudaFuncSetAttribute(proj_kernel,
                         cudaFuncAttributeMaxDynamicSharedMemorySize, PROJ_SMEM);
    cudaFuncSetAttribute(attn_kernel,
                         cudaFuncAttributeMaxDynamicSharedMemorySize, ATTN_SMEM);

    convw_kernel<<<32, 256>>>(U_w, V_w);
    proj_kernel<<<(B_ * N_) / 64, 512, PROJ_SMEM>>>(
        h_c, (const uint32_t*)pWuH, (const uint32_t*)pWuL, U_b,
        (__nv_bfloat16*)pUcH, (__nv_bfloat16*)pUcL);
    proj_kernel<<<(B_ * M_) / 64, 512, PROJ_SMEM>>>(
        h_p, (const uint32_t*)pWvH, (const uint32_t*)pWvL, V_b,
        (__nv_bfloat16*)pVpH, (__nv_bfloat16*)pVpL);
    attn_kernel<<<B_ * 16, 256, ATTN_SMEM>>>((float*)pPart);
    reduce_kernel<<<(B_ * D_) / 256, 256>>>((const float*)pPart, q, out);
}

// round 15
// speedup vs baseline: 1.2577x; 1.0131x over previous
#include <cuda_runtime.h>
#include <cuda_bf16.h>
#include <cstdint>

#define B_ 64
#define N_ 512
#define M_ 1024
#define D_ 128

typedef unsigned long long ull;

extern __shared__ char dynsm[];

// ---------------- device scratch (allocation-free) ----------------
// (Uc/Vp buffers hold fp16 hi/lo halves; declared as raw 2-byte storage)
__device__ __nv_bfloat16 g_UcHi[(size_t)B_ * N_ * D_];
__device__ __nv_bfloat16 g_UcLo[(size_t)B_ * N_ * D_];
__device__ __nv_bfloat16 g_VpHi[(size_t)B_ * M_ * D_];
__device__ __nv_bfloat16 g_VpLo[(size_t)B_ * M_ * D_];
__device__ uint32_t g_WuH[128 * 64], g_WuL[128 * 64];   // W as u32(bf16x2)
__device__ uint32_t g_WvH[128 * 64], g_WvL[128 * 64];
__device__ float g_part[(size_t)B_ * 16 * D_];

// ---------------- helpers ----------------
__device__ __forceinline__ uint32_t pack_bf16x2(float hi, float lo) {
    uint32_t r;
    asm("cvt.rn.bf16x2.f32 %0, %1, %2;" : "=r"(r) : "f"(hi), "f"(lo));
    return r;
}
__device__ __forceinline__ float lo_f(uint32_t p) { return __uint_as_float(p << 16); }
__device__ __forceinline__ float hi_f(uint32_t p) { return __uint_as_float(p & 0xffff0000u); }

__device__ __forceinline__ uint32_t pack_f16x2(float hi, float lo) {
    uint32_t r;
    asm("cvt.rn.f16x2.f32 %0, %1, %2;" : "=r"(r) : "f"(hi), "f"(lo));
    return r;
}
__device__ __forceinline__ float f16lo(uint32_t p) {
    float f;
    asm("{.reg .b16 l, h; mov.b32 {l, h}, %1; cvt.f32.f16 %0, l;}"
        : "=f"(f) : "r"(p));
    return f;
}
__device__ __forceinline__ float f16hi(uint32_t p) {
    float f;
    asm("{.reg .b16 l, h; mov.b32 {l, h}, %1; cvt.f32.f16 %0, h;}"
        : "=f"(f) : "r"(p));
    return f;
}

__device__ __forceinline__ uint32_t smem_u32(const void* p) {
    uint32_t a;
    asm("{ .reg .u64 t; cvta.to.shared.u64 t, %1; cvt.u32.u64 %0, t; }"
        : "=r"(a) : "l"(p));
    return a;
}
__device__ __forceinline__ void mma_bf16(float* c, uint32_t a0, uint32_t a1,
                                         uint32_t a2, uint32_t a3,
                                         uint32_t b0, uint32_t b1) {
    asm volatile(
        "mma.sync.aligned.m16n8k16.row.col.f32.bf16.bf16.f32 "
        "{%0,%1,%2,%3},{%4,%5,%6,%7},{%8,%9},{%0,%1,%2,%3};"
        : "+f"(c[0]), "+f"(c[1]), "+f"(c[2]), "+f"(c[3])
        : "r"(a0), "r"(a1), "r"(a2), "r"(a3), "r"(b0), "r"(b1));
}
__device__ __forceinline__ void mma_f16(float* c, uint32_t a0, uint32_t a1,
                                        uint32_t a2, uint32_t a3,
                                        uint32_t b0, uint32_t b1) {
    asm volatile(
        "mma.sync.aligned.m16n8k16.row.col.f32.f16.f16.f32 "
        "{%0,%1,%2,%3},{%4,%5,%6,%7},{%8,%9},{%0,%1,%2,%3};"
        : "+f"(c[0]), "+f"(c[1]), "+f"(c[2]), "+f"(c[3])
        : "r"(a0), "r"(a1), "r"(a2), "r"(a3), "r"(b0), "r"(b1));
}
__device__ __forceinline__ void ldsm_x4(uint32_t& r0, uint32_t& r1, uint32_t& r2,
                                        uint32_t& r3, uint32_t addr) {
    asm volatile("ldmatrix.sync.aligned.m8n8.x4.shared.b16 {%0,%1,%2,%3}, [%4];"
                 : "=r"(r0), "=r"(r1), "=r"(r2), "=r"(r3) : "r"(addr));
}
__device__ __forceinline__ void ldsm_x2(uint32_t& r0, uint32_t& r1, uint32_t addr) {
    asm volatile("ldmatrix.sync.aligned.m8n8.x2.shared.b16 {%0,%1}, [%2];"
                 : "=r"(r0), "=r"(r1) : "r"(addr));
}
__device__ __forceinline__ void ldsm_x4t(uint32_t& r0, uint32_t& r1, uint32_t& r2,
                                         uint32_t& r3, uint32_t addr) {
    asm volatile("ldmatrix.sync.aligned.m8n8.x4.trans.shared.b16 {%0,%1,%2,%3}, [%4];"
                 : "=r"(r0), "=r"(r1), "=r"(r2), "=r"(r3) : "r"(addr));
}
__device__ __forceinline__ void cpa16(uint32_t dst, const void* src) {
    asm volatile("cp.async.cg.shared.global [%0], [%1], 16;"
                 :: "r"(dst), "l"(src) : "memory");
}
#define CP_COMMIT() asm volatile("cp.async.commit_group;" ::: "memory")
#define CP_WAIT0() asm volatile("cp.async.wait_group 0;" ::: "memory")

// ============================================================================
// One-shot W conversion: fp32 -> bf16 hi/lo (for proj's internal bf16 MMA).
// ============================================================================
__global__ __launch_bounds__(256)
void convw_kernel(const float* __restrict__ Uw, const float* __restrict__ Vw) {
    int i = blockIdx.x * 256 + threadIdx.x;      // 0..8191
    int j = i & 4095;
    const float4* src = (i < 4096) ? (const float4*)Uw : (const float4*)Vw;
    uint32_t* dh = (i < 4096) ? g_WuH : g_WvH;
    uint32_t* dl = (i < 4096) ? g_WuL : g_WvL;
    float4 v = src[j];
    uint32_t h0 = pack_bf16x2(v.y, v.x);
    uint32_t l0 = pack_bf16x2(v.y - hi_f(h0), v.x - lo_f(h0));
    uint32_t h1 = pack_bf16x2(v.w, v.z);
    uint32_t l1 = pack_bf16x2(v.w - hi_f(h1), v.z - lo_f(h1));
    dh[j * 2] = h0; dh[j * 2 + 1] = h1;
    dl[j * 2] = l0; dl[j * 2 + 1] = l1;
}

// ============================================================================
// Merged projection via bf16 HMMA: relu(X @ W^T + b) -> fp16 hi/lo outputs.
// Grid 1536: blocks [0,512) compute Uc from h_c, [512,1536) compute Vp from h_p.
// ============================================================================
#define PJ_WH 0
#define PJ_WL 34816
#define PJ_XH 69632
#define PJ_XL 87040
#define PROJ_SMEM 104448

__global__ __launch_bounds__(512, 1)
void proj_kernel(const float* __restrict__ Xc, const float* __restrict__ Xp,
                 const float* __restrict__ Ubias, const float* __restrict__ Vbias) {
    char* sm = dynsm;
    const uint32_t smu = smem_u32(sm);
    const int tid = threadIdx.x, wid = tid >> 5, lane = tid & 31;
    const int wr = wid & 3, wc = wid >> 2;
    const int g = lane >> 2, t = lane & 3;
    const int blk = blockIdx.x;
    const bool isU = blk < 512;
    const float* X = isU ? Xc : Xp;
    const uint32_t* WHg = isU ? g_WuH : g_WvH;
    const uint32_t* WLg = isU ? g_WuL : g_WvL;
    const float* bias = isU ? Ubias : Vbias;
    uint32_t* oH = (uint32_t*)(isU ? g_UcHi : g_VpHi);
    uint32_t* oL = (uint32_t*)(isU ? g_UcLo : g_VpLo);
    const size_t row0 = (size_t)(isU ? blk : blk - 512) * 64;

    uint4* WHs = (uint4*)(sm + PJ_WH);
    uint4* WLs = (uint4*)(sm + PJ_WL);
    const uint4* WHg4 = (const uint4*)WHg;
    const uint4* WLg4 = (const uint4*)WLg;
    #pragma unroll
    for (int it = 0; it < 4; it++) {
        int i = it * 512 + tid;
        int r = i >> 4, c = i & 15;
        WHs[r * 17 + c] = WHg4[i];
        WLs[r * 17 + c] = WLg4[i];
    }
    uint32_t* XH = (uint32_t*)(sm + PJ_XH);
    uint32_t* XL = (uint32_t*)(sm + PJ_XL);
    const float4* Xg = (const float4*)(X + row0 * D_);
    #pragma unroll
    for (int it = 0; it < 4; it++) {
        int i = it * 512 + tid;
        int r = i >> 5, c4 = i & 31;
        float4 v = Xg[i];
        uint32_t h0 = pack_bf16x2(v.y, v.x);
        uint32_t l0 = pack_bf16x2(v.y - hi_f(h0), v.x - lo_f(h0));
        uint32_t h1 = pack_bf16x2(v.w, v.z);
        uint32_t l1 = pack_bf16x2(v.w - hi_f(h1), v.z - lo_f(h1));
        XH[r * 68 + c4 * 2] = h0; XH[r * 68 + c4 * 2 + 1] = h1;
        XL[r * 68 + c4 * 2] = l0; XL[r * 68 + c4 * 2 + 1] = l1;
    }
    __syncthreads();

    const int l7 = lane & 7, l8 = (lane >> 3) & 1, l16 = lane >> 4;
    const uint32_t aoffH = smu + PJ_XH + ((16 * wr + l7 + l8 * 8) * 68 + l16 * 4) * 4;
    const uint32_t aoffL = smu + PJ_XL + ((16 * wr + l7 + l8 * 8) * 68 + l16 * 4) * 4;
    const uint32_t boffH = smu + PJ_WH + ((wc * 32 + l7) * 68 + l8 * 4) * 4;
    const uint32_t boffL = smu + PJ_WL + ((wc * 32 + l7) * 68 + l8 * 4) * 4;

    float accA[4][4], accB[4][4];
    #pragma unroll
    for (int j = 0; j < 4; j++)
        #pragma unroll
        for (int q = 0; q < 4; q++) { accA[j][q] = 0.0f; accB[j][q] = 0.0f; }

    #pragma unroll
    for (int kk = 0; kk < 8; kk++) {
        uint32_t ah0, ah1, ah2, ah3, al0, al1, al2, al3;
        ldsm_x4(ah0, ah1, ah2, ah3, aoffH + kk * 32);
        ldsm_x4(al0, al1, al2, al3, aoffL + kk * 32);
        #pragma unroll
        for (int j = 0; j < 4; j++) {
            uint32_t bh0, bh1, bl0, bl1;
            ldsm_x2(bh0, bh1, boffH + j * 2176 + kk * 32);
            ldsm_x2(bl0, bl1, boffL + j * 2176 + kk * 32);
            mma_bf16(accA[j], ah0, ah1, ah2, ah3, bh0, bh1);
            mma_bf16(accB[j], ah0, ah1, ah2, ah3, bl0, bl1);
            mma_bf16(accB[j], al0, al1, al2, al3, bh0, bh1);
        }
    }

    // epilogue: bias + relu + fp16 hi/lo split
    const int rA = 16 * wr + g;
    const float2* b2 = (const float2*)bias;
    #pragma unroll
    for (int j = 0; j < 4; j++) {
        const int cpair = wc * 16 + j * 4 + t;
        float2 bb = b2[cpair];
        float o0 = fmaxf(accA[j][0] + accB[j][0] + bb.x, 0.0f);
        float o1 = fmaxf(accA[j][1] + accB[j][1] + bb.y, 0.0f);
        uint32_t h = pack_f16x2(o1, o0);
        uint32_t l = pack_f16x2(o1 - f16hi(h), o0 - f16lo(h));
        oH[(row0 + rA) * 64 + cpair] = h;
        oL[(row0 + rA) * 64 + cpair] = l;
        float o2 = fmaxf(accA[j][2] + accB[j][2] + bb.x, 0.0f);
        float o3 = fmaxf(accA[j][3] + accB[j][3] + bb.y, 0.0f);
        uint32_t h2 = pack_f16x2(o3, o2);
        uint32_t l2 = pack_f16x2(o3 - f16hi(h2), o2 - f16lo(h2));
        oH[(row0 + rA + 8) * 64 + cpair] = h2;
        oL[(row0 + rA + 8) * 64 + cpair] = l2;
    }
}

// ============================================================================
// Fused attention, fp16 + per-warp online max (lazy rescale):
// CTA = (b, 32-row n-tile), grid 1024, 256 thr, 2 CTAs/SM.
// Warp grid 2(n) x 4(m-slice). Scores: 3-term fp16 split. Ctx: SINGLE
// fp16 MMA (P_f16 x Vh_f16), k=16 per chunk, per-warp local max frame.
// ============================================================================
#define OFF_UCH 0
#define OFF_UCL 8704
#define OFF_VH0 17408
#define OFF_VL0 34816
#define OFF_VH1 52224
#define OFF_VL1 69632
#define OFF_MX  87040
#define OFF_RSS 87552
#define OFF_MXR 88064
#define OFF_INV 88192
#define OFF_RED 88320
#define ATTN_SMEM 89344

__global__ __launch_bounds__(256, 2)
void attn_kernel(float* __restrict__ part) {
    char* sm = dynsm;
    const uint32_t smu = smem_u32(sm);
    const int tid = threadIdx.x, wid = tid >> 5, lane = tid & 31;
    const int wr = wid & 1, wc = wid >> 1;          // 2 x 4 warp grid
    const int g = lane >> 2, t = lane & 3;
    const int b = blockIdx.x >> 4, nt = blockIdx.x & 15;

    uint32_t* UC32h = (uint32_t*)(sm + OFF_UCH);   // 32 rows, stride 68 u32
    uint32_t* UC32l = (uint32_t*)(sm + OFF_UCL);
    float* MXs = (float*)(sm + OFF_MX);
    float* RSs = (float*)(sm + OFF_RSS);
    float* MXR = (float*)(sm + OFF_MXR);
    float* INV = (float*)(sm + OFF_INV);
    float* RED = (float*)(sm + OFF_RED);

    const uint4* ucHg = (const uint4*)(g_UcHi + ((size_t)(b * N_ + nt * 32)) * D_);
    const uint4* ucLg = (const uint4*)(g_UcLo + ((size_t)(b * N_ + nt * 32)) * D_);
    const uint4* vpHg = (const uint4*)(g_VpHi + (size_t)b * M_ * D_);
    const uint4* vpLg = (const uint4*)(g_VpLo + (size_t)b * M_ * D_);

    // stage Uc (32 rows x 16 uint4 per buffer)
    uint4* UH4 = (uint4*)(sm + OFF_UCH);
    uint4* UL4 = (uint4*)(sm + OFF_UCL);
    #pragma unroll
    for (int it = 0; it < 2; it++) {
        int i = it * 256 + tid;
        int r = i >> 4, c = i & 15;
        UH4[r * 17 + c] = ucHg[i];
        UL4[r * 17 + c] = ucLg[i];
    }

    const uint32_t vhB[2] = {smu + OFF_VH0, smu + OFF_VH1};
    const uint32_t vlB[2] = {smu + OFF_VL0, smu + OFF_VL1};

    const int l7 = lane & 7, l8 = (lane >> 3) & 1, l16 = lane >> 4;
    const uint32_t aoffH = smu + OFF_UCH + ((16 * wr + l7 + l8 * 8) * 68 + l16 * 4) * 4;
    const uint32_t aoffL = smu + OFF_UCL + ((16 * wr + l7 + l8 * 8) * 68 + l16 * 4) * 4;
    const uint32_t boffV4 = ((wc * 16 + l16 * 8 + l7) * 68 + l8 * 4) * 4;
    const uint32_t boffT4 = ((wc * 16 + l8 * 8 + l7) * 68) * 4 + l16 * 16;

    // hoisted cp.async per-thread addressing (i = it*256+tid)
    const uint32_t cpdst = ((tid >> 4) * 68 + (tid & 15) * 4) * 4;  // + it*4352
    const int cpsrc = (tid >> 4) * 16 + (tid & 15);                  // + it*256

    const int rA = 16 * wr + g;
    float cacc[16][4];
    #pragma unroll
    for (int j = 0; j < 16; j++)
        #pragma unroll
        for (int q = 0; q < 4; q++) cacc[j][q] = 0.0f;
    float rs0 = 0.0f, rs1 = 0.0f;
    float mx0 = 0.0f, mx1 = 0.0f;     // scores >= 0 (ReLU operands)

    // stage chunk 0
    #pragma unroll
    for (int it = 0; it < 4; it++) {
        cpa16(vhB[0] + cpdst + it * 4352, vpHg + cpsrc + it * 256);
        cpa16(vlB[0] + cpdst + it * 4352, vpLg + cpsrc + it * 256);
    }
    CP_COMMIT();

    for (int mc = 0; mc < 16; mc++) {
        const int s = mc & 1;
        CP_WAIT0();
        __syncthreads();
        if (mc + 1 < 16) {
            const int s2 = s ^ 1;
            const int srcb = cpsrc + (mc + 1) * 1024;
            #pragma unroll
            for (int it = 0; it < 4; it++) {
                cpa16(vhB[s2] + cpdst + it * 4352, vpHg + srcb + it * 256);
                cpa16(vlB[s2] + cpdst + it * 4352, vpLg + srcb + it * 256);
            }
            CP_COMMIT();
        }

        // ---- scores: 16n x 16m (own m-slice), k=128, fp16 3-term ----
        float accA[2][4], accB[2][4];
        #pragma unroll
        for (int j = 0; j < 2; j++)
            #pragma unroll
            for (int q = 0; q < 4; q++) { accA[j][q] = 0.0f; accB[j][q] = 0.0f; }

        const uint32_t bvh = vhB[s] + boffV4, bvl = vlB[s] + boffV4;
        #pragma unroll
        for (int kk = 0; kk < 8; kk++) {
            uint32_t ah0, ah1, ah2, ah3, al0, al1, al2, al3;
            ldsm_x4(ah0, ah1, ah2, ah3, aoffH + kk * 32);
            ldsm_x4(al0, al1, al2, al3, aoffL + kk * 32);
            uint32_t bh0, bh1, bh2, bh3, bl0, bl1, bl2, bl3;
            ldsm_x4(bh0, bh1, bh2, bh3, bvh + kk * 32);
            ldsm_x4(bl0, bl1, bl2, bl3, bvl + kk * 32);
            mma_f16(accA[0], ah0, ah1, ah2, ah3, bh0, bh1);
            mma_f16(accB[0], ah0, ah1, ah2, ah3, bl0, bl1);
            mma_f16(accB[0], al0, al1, al2, al3, bh0, bh1);
            mma_f16(accA[1], ah0, ah1, ah2, ah3, bh2, bh3);
            mma_f16(accB[1], ah0, ah1, ah2, ah3, bl2, bl3);
            mma_f16(accB[1], al0, al1, al2, al3, bh2, bh3);
        }

        // ---- per-warp online max (lazy rescale) + exp + fp16 P pack ----
        float s00 = accA[0][0] + accB[0][0], s01 = accA[0][1] + accB[0][1];
        float s02 = accA[0][2] + accB[0][2], s03 = accA[0][3] + accB[0][3];
        float s10 = accA[1][0] + accB[1][0], s11 = accA[1][1] + accB[1][1];
        float s12 = accA[1][2] + accB[1][2], s13 = accA[1][3] + accB[1][3];
        float c0 = fmaxf(fmaxf(s00, s01), fmaxf(s10, s11));
        float c1 = fmaxf(fmaxf(s02, s03), fmaxf(s12, s13));
        c0 = fmaxf(c0, __shfl_xor_sync(0xffffffffu, c0, 1));
        c0 = fmaxf(c0, __shfl_xor_sync(0xffffffffu, c0, 2));
        c1 = fmaxf(c1, __shfl_xor_sync(0xffffffffu, c1, 1));
        c1 = fmaxf(c1, __shfl_xor_sync(0xffffffffu, c1, 2));
        if (c0 > mx0 || c1 > mx1) {   // warp-uniform branch
            float nm0 = fmaxf(mx0, c0), nm1 = fmaxf(mx1, c1);
            float scl0 = __expf(mx0 - nm0), scl1 = __expf(mx1 - nm1);
            rs0 *= scl0; rs1 *= scl1;
            #pragma unroll
            for (int j = 0; j < 16; j++) {
                cacc[j][0] *= scl0; cacc[j][1] *= scl0;
                cacc[j][2] *= scl1; cacc[j][3] *= scl1;
            }
            mx0 = nm0; mx1 = nm1;
        }
        float e0 = __expf(s00 - mx0), e1 = __expf(s01 - mx0);
        float f0 = __expf(s10 - mx0), f1 = __expf(s11 - mx0);
        float e2 = __expf(s02 - mx1), e3 = __expf(s03 - mx1);
        float f2 = __expf(s12 - mx1), f3 = __expf(s13 - mx1);
        rs0 += e0 + e1 + f0 + f1;
        rs1 += e2 + e3 + f2 + f3;
        uint32_t ph0 = pack_f16x2(e1, e0);
        uint32_t ph1 = pack_f16x2(e3, e2);
        uint32_t ph2 = pack_f16x2(f1, f0);
        uint32_t ph3 = pack_f16x2(f3, f2);

        // ---- ctx partial: 16n x 128d, k=16, SINGLE-term fp16 ----
        const uint32_t bth = vhB[s] + boffT4;
        #pragma unroll
        for (int j = 0; j < 16; j += 2) {
            uint32_t b0, b1, b2, b3;
            ldsm_x4t(b0, b1, b2, b3, bth + j * 16);
            mma_f16(cacc[j],     ph0, ph1, ph2, ph3, b0, b1);
            mma_f16(cacc[j + 1], ph0, ph1, ph2, ph3, b2, b3);
        }
    }

    // ---- per-warp (mx, rs) -> smem; merge frames across wc ----
    rs0 += __shfl_xor_sync(0xffffffffu, rs0, 1);
    rs0 += __shfl_xor_sync(0xffffffffu, rs0, 2);
    rs1 += __shfl_xor_sync(0xffffffffu, rs1, 1);
    rs1 += __shfl_xor_sync(0xffffffffu, rs1, 2);
    if (t == 0) {
        MXs[wc * 32 + rA] = mx0;  MXs[wc * 32 + rA + 8] = mx1;
        RSs[wc * 32 + rA] = rs0;  RSs[wc * 32 + rA + 8] = rs1;
    }
    __syncthreads();
    if (tid < 32) {
        float m0 = MXs[tid], m1 = MXs[32 + tid];
        float m2 = MXs[64 + tid], m3 = MXs[96 + tid];
        float M = fmaxf(fmaxf(m0, m1), fmaxf(m2, m3));
        float R = RSs[tid] * __expf(m0 - M) + RSs[32 + tid] * __expf(m1 - M) +
                  RSs[64 + tid] * __expf(m2 - M) + RSs[96 + tid] * __expf(m3 - M);
        MXR[tid] = M;
        INV[tid] = 1.0f / R;
    }
    __syncthreads();

    const float sc0 = __expf(mx0 - MXR[rA]);
    const float sc1 = __expf(mx1 - MXR[rA + 8]);

    // ---- sum scaled ctx partials over wc into Jt ----
    float* Jt = (float*)(sm + OFF_VH0);   // 32 x 132 f32 (reuses V area)
    #pragma unroll
    for (int p = 0; p < 4; p++) {
        if (wc == p) {
            #pragma unroll
            for (int j = 0; j < 16; j++) {
                const int d0 = j * 8 + 2 * t;
                if (p == 0) {
                    Jt[rA * 132 + d0]           = cacc[j][0] * sc0;
                    Jt[rA * 132 + d0 + 1]       = cacc[j][1] * sc0;
                    Jt[(rA + 8) * 132 + d0]     = cacc[j][2] * sc1;
                    Jt[(rA + 8) * 132 + d0 + 1] = cacc[j][3] * sc1;
                } else {
                    Jt[rA * 132 + d0]           += cacc[j][0] * sc0;
                    Jt[rA * 132 + d0 + 1]       += cacc[j][1] * sc0;
                    Jt[(rA + 8) * 132 + d0]     += cacc[j][2] * sc1;
                    Jt[(rA + 8) * 132 + d0 + 1] += cacc[j][3] * sc1;
                }
            }
        }
        __syncthreads();
    }

    // ---- n-reduce: sum over rows of (Uc + ctx*inv) ----
    {
        int h = tid >> 7, d = tid & 127;   // 2 groups x 16 rows
        float s = 0.0f;
        #pragma unroll
        for (int r = 0; r < 16; r++) {
            int row = h * 16 + r;
            uint32_t uh = UC32h[row * 68 + (d >> 1)];
            uint32_t ul = UC32l[row * 68 + (d >> 1)];
            float uc = (d & 1) ? (f16hi(uh) + f16hi(ul)) : (f16lo(uh) + f16lo(ul));
            s += uc + Jt[row * 132 + d] * INV[row];
        }
        RED[h * 128 + d] = s;
    }
    __syncthreads();
    if (tid < 128)
        part[(size_t)blockIdx.x * D_ + tid] = RED[tid] + RED[128 + tid];
}

// ============================================================================
__global__ __launch_bounds__(256)
void reduce_kernel(const float* __restrict__ part, const float* __restrict__ q,
                   float* __restrict__ out) {
    int i = blockIdx.x * blockDim.x + threadIdx.x;
    int b = i >> 7, d = i & 127;
    float s = 0.0f;
    #pragma unroll
    for (int nt = 0; nt < 16; nt++)
        s += part[(size_t)(b * 16 + nt) * D_ + d];
    out[i] = s * q[d] * (1.0f / (float)N_);
}

// ============================================================================
extern "C" void kernel_launch(void* const* d_in, const int* in_sizes, int n_in,
                              void* d_out, int out_size) {
    const float* h_c = (const float*)d_in[0];
    const float* h_p = (const float*)d_in[1];
    const float* U_w = (const float*)d_in[2];
    const float* U_b = (const float*)d_in[3];
    const float* V_w = (const float*)d_in[4];
    const float* V_b = (const float*)d_in[5];
    const float* q   = (const float*)d_in[6];
    float* out = (float*)d_out;

    void *pPart;
    cudaGetSymbolAddress(&pPart, g_part);

    cudaFuncSetAttribute(proj_kernel,
                         cudaFuncAttributeMaxDynamicSharedMemorySize, PROJ_SMEM);
    cudaFuncSetAttribute(attn_kernel,
                         cudaFuncAttributeMaxDynamicSharedMemorySize, ATTN_SMEM);

    convw_kernel<<<32, 256>>>(U_w, V_w);
    proj_kernel<<<1536, 512, PROJ_SMEM>>>(h_c, h_p, U_b, V_b);
    attn_kernel<<<B_ * 16, 256, ATTN_SMEM>>>((float*)pPart);
    reduce_kernel<<<(B_ * D_) / 256, 256>>>((const float*)pPart, q, out);
}

// round 16
// speedup vs baseline: 1.2994x; 1.0331x over previous
#include <cuda_runtime.h>
#include <cuda_bf16.h>
#include <cstdint>

#define B_ 64
#define N_ 512
#define M_ 1024
#define D_ 128

typedef unsigned long long ull;

extern __shared__ char dynsm[];

// ---------------- device scratch (allocation-free) ----------------
// (Uc/Vp buffers hold fp16 hi/lo halves; declared as raw 2-byte storage)
__device__ __nv_bfloat16 g_UcHi[(size_t)B_ * N_ * D_];
__device__ __nv_bfloat16 g_UcLo[(size_t)B_ * N_ * D_];
__device__ __nv_bfloat16 g_VpHi[(size_t)B_ * M_ * D_];
__device__ __nv_bfloat16 g_VpLo[(size_t)B_ * M_ * D_];
__device__ uint32_t g_WuH[128 * 64], g_WuL[128 * 64];   // W as u32(bf16x2)
__device__ uint32_t g_WvH[128 * 64], g_WvL[128 * 64];
__device__ float g_part[(size_t)B_ * 16 * D_];

// ---------------- helpers ----------------
__device__ __forceinline__ uint32_t pack_bf16x2(float hi, float lo) {
    uint32_t r;
    asm("cvt.rn.bf16x2.f32 %0, %1, %2;" : "=r"(r) : "f"(hi), "f"(lo));
    return r;
}
__device__ __forceinline__ float lo_f(uint32_t p) { return __uint_as_float(p << 16); }
__device__ __forceinline__ float hi_f(uint32_t p) { return __uint_as_float(p & 0xffff0000u); }

__device__ __forceinline__ uint32_t pack_f16x2(float hi, float lo) {
    uint32_t r;
    asm("cvt.rn.f16x2.f32 %0, %1, %2;" : "=r"(r) : "f"(hi), "f"(lo));
    return r;
}
__device__ __forceinline__ float f16lo(uint32_t p) {
    float f;
    asm("{.reg .b16 l, h; mov.b32 {l, h}, %1; cvt.f32.f16 %0, l;}"
        : "=f"(f) : "r"(p));
    return f;
}
__device__ __forceinline__ float f16hi(uint32_t p) {
    float f;
    asm("{.reg .b16 l, h; mov.b32 {l, h}, %1; cvt.f32.f16 %0, h;}"
        : "=f"(f) : "r"(p));
    return f;
}

__device__ __forceinline__ uint32_t smem_u32(const void* p) {
    uint32_t a;
    asm("{ .reg .u64 t; cvta.to.shared.u64 t, %1; cvt.u32.u64 %0, t; }"
        : "=r"(a) : "l"(p));
    return a;
}
__device__ __forceinline__ void mma_bf16(float* c, uint32_t a0, uint32_t a1,
                                         uint32_t a2, uint32_t a3,
                                         uint32_t b0, uint32_t b1) {
    asm volatile(
        "mma.sync.aligned.m16n8k16.row.col.f32.bf16.bf16.f32 "
        "{%0,%1,%2,%3},{%4,%5,%6,%7},{%8,%9},{%0,%1,%2,%3};"
        : "+f"(c[0]), "+f"(c[1]), "+f"(c[2]), "+f"(c[3])
        : "r"(a0), "r"(a1), "r"(a2), "r"(a3), "r"(b0), "r"(b1));
}
__device__ __forceinline__ void mma_f16(float* c, uint32_t a0, uint32_t a1,
                                        uint32_t a2, uint32_t a3,
                                        uint32_t b0, uint32_t b1) {
    asm volatile(
        "mma.sync.aligned.m16n8k16.row.col.f32.f16.f16.f32 "
        "{%0,%1,%2,%3},{%4,%5,%6,%7},{%8,%9},{%0,%1,%2,%3};"
        : "+f"(c[0]), "+f"(c[1]), "+f"(c[2]), "+f"(c[3])
        : "r"(a0), "r"(a1), "r"(a2), "r"(a3), "r"(b0), "r"(b1));
}
// fp16-accumulator variant (C as 2 packed f16x2 regs) for small cross terms
__device__ __forceinline__ void mma_f16c16(uint32_t& c0, uint32_t& c1,
                                           uint32_t a0, uint32_t a1,
                                           uint32_t a2, uint32_t a3,
                                           uint32_t b0, uint32_t b1) {
    asm volatile(
        "mma.sync.aligned.m16n8k16.row.col.f16.f16.f16.f16 "
        "{%0,%1},{%2,%3,%4,%5},{%6,%7},{%0,%1};"
        : "+r"(c0), "+r"(c1)
        : "r"(a0), "r"(a1), "r"(a2), "r"(a3), "r"(b0), "r"(b1));
}
__device__ __forceinline__ void ldsm_x4(uint32_t& r0, uint32_t& r1, uint32_t& r2,
                                        uint32_t& r3, uint32_t addr) {
    asm volatile("ldmatrix.sync.aligned.m8n8.x4.shared.b16 {%0,%1,%2,%3}, [%4];"
                 : "=r"(r0), "=r"(r1), "=r"(r2), "=r"(r3) : "r"(addr));
}
__device__ __forceinline__ void ldsm_x2(uint32_t& r0, uint32_t& r1, uint32_t addr) {
    asm volatile("ldmatrix.sync.aligned.m8n8.x2.shared.b16 {%0,%1}, [%2];"
                 : "=r"(r0), "=r"(r1) : "r"(addr));
}
__device__ __forceinline__ void ldsm_x4t(uint32_t& r0, uint32_t& r1, uint32_t& r2,
                                         uint32_t& r3, uint32_t addr) {
    asm volatile("ldmatrix.sync.aligned.m8n8.x4.trans.shared.b16 {%0,%1,%2,%3}, [%4];"
                 : "=r"(r0), "=r"(r1), "=r"(r2), "=r"(r3) : "r"(addr));
}
__device__ __forceinline__ void cpa16(uint32_t dst, const void* src) {
    asm volatile("cp.async.cg.shared.global [%0], [%1], 16;"
                 :: "r"(dst), "l"(src) : "memory");
}
#define CP_COMMIT() asm volatile("cp.async.commit_group;" ::: "memory")
#define CP_WAIT0() asm volatile("cp.async.wait_group 0;" ::: "memory")

// ============================================================================
// One-shot W conversion: fp32 -> bf16 hi/lo (for proj's internal bf16 MMA).
// ============================================================================
__global__ __launch_bounds__(256)
void convw_kernel(const float* __restrict__ Uw, const float* __restrict__ Vw) {
    int i = blockIdx.x * 256 + threadIdx.x;      // 0..8191
    int j = i & 4095;
    const float4* src = (i < 4096) ? (const float4*)Uw : (const float4*)Vw;
    uint32_t* dh = (i < 4096) ? g_WuH : g_WvH;
    uint32_t* dl = (i < 4096) ? g_WuL : g_WvL;
    float4 v = src[j];
    uint32_t h0 = pack_bf16x2(v.y, v.x);
    uint32_t l0 = pack_bf16x2(v.y - hi_f(h0), v.x - lo_f(h0));
    uint32_t h1 = pack_bf16x2(v.w, v.z);
    uint32_t l1 = pack_bf16x2(v.w - hi_f(h1), v.z - lo_f(h1));
    dh[j * 2] = h0; dh[j * 2 + 1] = h1;
    dl[j * 2] = l0; dl[j * 2 + 1] = l1;
}

// ============================================================================
// Merged projection via bf16 HMMA: relu(X @ W^T + b) -> fp16 hi/lo.
// 128-row CTAs: W staged ONCE, two 64-row X blocks processed in place.
// Grid 768: blocks [0,256) -> Uc from h_c, [256,768) -> Vp from h_p.
// ============================================================================
#define PJ_WH 0
#define PJ_WL 34816
#define PJ_XH 69632
#define PJ_XL 87040
#define PROJ_SMEM 104448

__global__ __launch_bounds__(512, 1)
void proj_kernel(const float* __restrict__ Xc, const float* __restrict__ Xp,
                 const float* __restrict__ Ubias, const float* __restrict__ Vbias) {
    char* sm = dynsm;
    const uint32_t smu = smem_u32(sm);
    const int tid = threadIdx.x, wid = tid >> 5, lane = tid & 31;
    const int wr = wid & 3, wc = wid >> 2;
    const int g = lane >> 2, t = lane & 3;
    const int blk = blockIdx.x;
    const bool isU = blk < 256;
    const float* X = isU ? Xc : Xp;
    const uint32_t* WHg = isU ? g_WuH : g_WvH;
    const uint32_t* WLg = isU ? g_WuL : g_WvL;
    const float* bias = isU ? Ubias : Vbias;
    uint32_t* oH = (uint32_t*)(isU ? g_UcHi : g_VpHi);
    uint32_t* oL = (uint32_t*)(isU ? g_UcLo : g_VpLo);
    const size_t row0 = (size_t)(isU ? blk : blk - 256) * 128;

    // stage W once
    uint4* WHs = (uint4*)(sm + PJ_WH);
    uint4* WLs = (uint4*)(sm + PJ_WL);
    const uint4* WHg4 = (const uint4*)WHg;
    const uint4* WLg4 = (const uint4*)WLg;
    #pragma unroll
    for (int it = 0; it < 4; it++) {
        int i = it * 512 + tid;
        int r = i >> 4, c = i & 15;
        WHs[r * 17 + c] = WHg4[i];
        WLs[r * 17 + c] = WLg4[i];
    }

    const int l7 = lane & 7, l8 = (lane >> 3) & 1, l16 = lane >> 4;
    const uint32_t aoffH = smu + PJ_XH + ((16 * wr + l7 + l8 * 8) * 68 + l16 * 4) * 4;
    const uint32_t aoffL = smu + PJ_XL + ((16 * wr + l7 + l8 * 8) * 68 + l16 * 4) * 4;
    const uint32_t boffH = smu + PJ_WH + ((wc * 32 + l7) * 68 + l8 * 4) * 4;
    const uint32_t boffL = smu + PJ_WL + ((wc * 32 + l7) * 68 + l8 * 4) * 4;
    const int rA = 16 * wr + g;
    const float2* b2 = (const float2*)bias;
    uint32_t* XH = (uint32_t*)(sm + PJ_XH);
    uint32_t* XL = (uint32_t*)(sm + PJ_XL);

    #pragma unroll
    for (int rb = 0; rb < 2; rb++) {
        // stage X block (64 x 128)
        const float4* Xg = (const float4*)(X + (row0 + rb * 64) * D_);
        #pragma unroll
        for (int it = 0; it < 4; it++) {
            int i = it * 512 + tid;
            int r = i >> 5, c4 = i & 31;
            float4 v = Xg[i];
            uint32_t h0 = pack_bf16x2(v.y, v.x);
            uint32_t l0 = pack_bf16x2(v.y - hi_f(h0), v.x - lo_f(h0));
            uint32_t h1 = pack_bf16x2(v.w, v.z);
            uint32_t l1 = pack_bf16x2(v.w - hi_f(h1), v.z - lo_f(h1));
            XH[r * 68 + c4 * 2] = h0; XH[r * 68 + c4 * 2 + 1] = h1;
            XL[r * 68 + c4 * 2] = l0; XL[r * 68 + c4 * 2 + 1] = l1;
        }
        __syncthreads();

        float accA[4][4], accB[4][4];
        #pragma unroll
        for (int j = 0; j < 4; j++)
            #pragma unroll
            for (int q = 0; q < 4; q++) { accA[j][q] = 0.0f; accB[j][q] = 0.0f; }

        #pragma unroll
        for (int kk = 0; kk < 8; kk++) {
            uint32_t ah0, ah1, ah2, ah3, al0, al1, al2, al3;
            ldsm_x4(ah0, ah1, ah2, ah3, aoffH + kk * 32);
            ldsm_x4(al0, al1, al2, al3, aoffL + kk * 32);
            #pragma unroll
            for (int j = 0; j < 4; j++) {
                uint32_t bh0, bh1, bl0, bl1;
                ldsm_x2(bh0, bh1, boffH + j * 2176 + kk * 32);
                ldsm_x2(bl0, bl1, boffL + j * 2176 + kk * 32);
                mma_bf16(accA[j], ah0, ah1, ah2, ah3, bh0, bh1);
                mma_bf16(accB[j], ah0, ah1, ah2, ah3, bl0, bl1);
                mma_bf16(accB[j], al0, al1, al2, al3, bh0, bh1);
            }
        }

        // epilogue: bias + relu + fp16 hi/lo split (regs only)
        const size_t rbase = row0 + rb * 64;
        #pragma unroll
        for (int j = 0; j < 4; j++) {
            const int cpair = wc * 16 + j * 4 + t;
            float2 bb = b2[cpair];
            float o0 = fmaxf(accA[j][0] + accB[j][0] + bb.x, 0.0f);
            float o1 = fmaxf(accA[j][1] + accB[j][1] + bb.y, 0.0f);
            uint32_t h = pack_f16x2(o1, o0);
            uint32_t l = pack_f16x2(o1 - f16hi(h), o0 - f16lo(h));
            oH[(rbase + rA) * 64 + cpair] = h;
            oL[(rbase + rA) * 64 + cpair] = l;
            float o2 = fmaxf(accA[j][2] + accB[j][2] + bb.x, 0.0f);
            float o3 = fmaxf(accA[j][3] + accB[j][3] + bb.y, 0.0f);
            uint32_t h2 = pack_f16x2(o3, o2);
            uint32_t l2 = pack_f16x2(o3 - f16hi(h2), o2 - f16lo(h2));
            oH[(rbase + rA + 8) * 64 + cpair] = h2;
            oL[(rbase + rA + 8) * 64 + cpair] = l2;
        }
        __syncthreads();
    }
}

// ============================================================================
// Fused attention, fp16, online max (lazy rescale), fp16 cross accumulators,
// parallel epilogue. CTA = (b, 32-row n-tile), grid 1024, 256 thr, 2 CTAs/SM.
// ============================================================================
#define OFF_UCH 0
#define OFF_UCL 8704
#define OFF_VH0 17408
#define OFF_VL0 34816
#define OFF_VH1 52224
#define OFF_VL1 69632
#define OFF_MX  87040
#define OFF_RSS 87552
#define OFF_MXR 88064
#define OFF_INV 88192
#define OFF_RED 88320
#define ATTN_SMEM 89344

__global__ __launch_bounds__(256, 2)
void attn_kernel(float* __restrict__ part) {
    char* sm = dynsm;
    const uint32_t smu = smem_u32(sm);
    const int tid = threadIdx.x, wid = tid >> 5, lane = tid & 31;
    const int wr = wid & 1, wc = wid >> 1;          // 2 x 4 warp grid
    const int g = lane >> 2, t = lane & 3;
    const int b = blockIdx.x >> 4, nt = blockIdx.x & 15;

    uint32_t* UC32h = (uint32_t*)(sm + OFF_UCH);   // 32 rows, stride 68 u32
    uint32_t* UC32l = (uint32_t*)(sm + OFF_UCL);
    float* MXs = (float*)(sm + OFF_MX);
    float* RSs = (float*)(sm + OFF_RSS);
    float* MXR = (float*)(sm + OFF_MXR);
    float* INV = (float*)(sm + OFF_INV);
    float* RED = (float*)(sm + OFF_RED);

    const uint4* ucHg = (const uint4*)(g_UcHi + ((size_t)(b * N_ + nt * 32)) * D_);
    const uint4* ucLg = (const uint4*)(g_UcLo + ((size_t)(b * N_ + nt * 32)) * D_);
    const uint4* vpHg = (const uint4*)(g_VpHi + (size_t)b * M_ * D_);
    const uint4* vpLg = (const uint4*)(g_VpLo + (size_t)b * M_ * D_);

    const uint32_t vhB[2] = {smu + OFF_VH0, smu + OFF_VH1};
    const uint32_t vlB[2] = {smu + OFF_VL0, smu + OFF_VL1};

    const int l7 = lane & 7, l8 = (lane >> 3) & 1, l16 = lane >> 4;
    const uint32_t aoffH = smu + OFF_UCH + ((16 * wr + l7 + l8 * 8) * 68 + l16 * 4) * 4;
    const uint32_t aoffL = smu + OFF_UCL + ((16 * wr + l7 + l8 * 8) * 68 + l16 * 4) * 4;
    const uint32_t boffV4 = ((wc * 16 + l16 * 8 + l7) * 68 + l8 * 4) * 4;
    const uint32_t boffT4 = ((wc * 16 + l8 * 8 + l7) * 68) * 4 + l16 * 16;

    // hoisted cp.async per-thread addressing (i = it*256+tid)
    const uint32_t cpdst = ((tid >> 4) * 68 + (tid & 15) * 4) * 4;  // + it*4352
    const int cpsrc = tid;                                           // + it*256

    const int rA = 16 * wr + g;
    float cacc[16][4];
    #pragma unroll
    for (int j = 0; j < 16; j++)
        #pragma unroll
        for (int q = 0; q < 4; q++) cacc[j][q] = 0.0f;
    float rs0 = 0.0f, rs1 = 0.0f;
    float mx0 = 0.0f, mx1 = 0.0f;     // scores >= 0 (ReLU operands)

    // stage Uc (cp.async) + chunk 0 V, single commit
    #pragma unroll
    for (int it = 0; it < 2; it++) {
        cpa16(smu + OFF_UCH + cpdst + it * 4352, ucHg + cpsrc + it * 256);
        cpa16(smu + OFF_UCL + cpdst + it * 4352, ucLg + cpsrc + it * 256);
    }
    #pragma unroll
    for (int it = 0; it < 4; it++) {
        cpa16(vhB[0] + cpdst + it * 4352, vpHg + cpsrc + it * 256);
        cpa16(vlB[0] + cpdst + it * 4352, vpLg + cpsrc + it * 256);
    }
    CP_COMMIT();

    for (int mc = 0; mc < 16; mc++) {
        const int s = mc & 1;
        CP_WAIT0();
        __syncthreads();
        if (mc + 1 < 16) {
            const int s2 = s ^ 1;
            const int srcb = cpsrc + (mc + 1) * 1024;
            #pragma unroll
            for (int it = 0; it < 4; it++) {
                cpa16(vhB[s2] + cpdst + it * 4352, vpHg + srcb + it * 256);
                cpa16(vlB[s2] + cpdst + it * 4352, vpLg + srcb + it * 256);
            }
            CP_COMMIT();
        }

        // ---- scores: 16n x 16m (own m-slice), k=128, fp16 3-term ----
        float accA[2][4];
        uint32_t accB[2][2];
        #pragma unroll
        for (int j = 0; j < 2; j++) {
            #pragma unroll
            for (int q = 0; q < 4; q++) accA[j][q] = 0.0f;
            accB[j][0] = 0u; accB[j][1] = 0u;
        }

        const uint32_t bvh = vhB[s] + boffV4, bvl = vlB[s] + boffV4;
        #pragma unroll
        for (int kk = 0; kk < 8; kk++) {
            uint32_t ah0, ah1, ah2, ah3, al0, al1, al2, al3;
            ldsm_x4(ah0, ah1, ah2, ah3, aoffH + kk * 32);
            ldsm_x4(al0, al1, al2, al3, aoffL + kk * 32);
            uint32_t bh0, bh1, bh2, bh3, bl0, bl1, bl2, bl3;
            ldsm_x4(bh0, bh1, bh2, bh3, bvh + kk * 32);
            ldsm_x4(bl0, bl1, bl2, bl3, bvl + kk * 32);
            mma_f16(accA[0], ah0, ah1, ah2, ah3, bh0, bh1);
            mma_f16c16(accB[0][0], accB[0][1], ah0, ah1, ah2, ah3, bl0, bl1);
            mma_f16c16(accB[0][0], accB[0][1], al0, al1, al2, al3, bh0, bh1);
            mma_f16(accA[1], ah0, ah1, ah2, ah3, bh2, bh3);
            mma_f16c16(accB[1][0], accB[1][1], ah0, ah1, ah2, ah3, bl2, bl3);
            mma_f16c16(accB[1][0], accB[1][1], al0, al1, al2, al3, bh2, bh3);
        }

        // ---- per-warp online max (lazy rescale) + exp + fp16 P pack ----
        float s00 = accA[0][0] + f16lo(accB[0][0]);
        float s01 = accA[0][1] + f16hi(accB[0][0]);
        float s02 = accA[0][2] + f16lo(accB[0][1]);
        float s03 = accA[0][3] + f16hi(accB[0][1]);
        float s10 = accA[1][0] + f16lo(accB[1][0]);
        float s11 = accA[1][1] + f16hi(accB[1][0]);
        float s12 = accA[1][2] + f16lo(accB[1][1]);
        float s13 = accA[1][3] + f16hi(accB[1][1]);
        float c0 = fmaxf(fmaxf(s00, s01), fmaxf(s10, s11));
        float c1 = fmaxf(fmaxf(s02, s03), fmaxf(s12, s13));
        c0 = fmaxf(c0, __shfl_xor_sync(0xffffffffu, c0, 1));
        c0 = fmaxf(c0, __shfl_xor_sync(0xffffffffu, c0, 2));
        c1 = fmaxf(c1, __shfl_xor_sync(0xffffffffu, c1, 1));
        c1 = fmaxf(c1, __shfl_xor_sync(0xffffffffu, c1, 2));
        if (c0 > mx0 || c1 > mx1) {   // warp-uniform branch
            float nm0 = fmaxf(mx0, c0), nm1 = fmaxf(mx1, c1);
            float scl0 = __expf(mx0 - nm0), scl1 = __expf(mx1 - nm1);
            rs0 *= scl0; rs1 *= scl1;
            #pragma unroll
            for (int j = 0; j < 16; j++) {
                cacc[j][0] *= scl0; cacc[j][1] *= scl0;
                cacc[j][2] *= scl1; cacc[j][3] *= scl1;
            }
            mx0 = nm0; mx1 = nm1;
        }
        float e0 = __expf(s00 - mx0), e1 = __expf(s01 - mx0);
        float f0 = __expf(s10 - mx0), f1 = __expf(s11 - mx0);
        float e2 = __expf(s02 - mx1), e3 = __expf(s03 - mx1);
        float f2 = __expf(s12 - mx1), f3 = __expf(s13 - mx1);
        rs0 += e0 + e1 + f0 + f1;
        rs1 += e2 + e3 + f2 + f3;
        uint32_t ph0 = pack_f16x2(e1, e0);
        uint32_t ph1 = pack_f16x2(e3, e2);
        uint32_t ph2 = pack_f16x2(f1, f0);
        uint32_t ph3 = pack_f16x2(f3, f2);

        // ---- ctx partial: 16n x 128d, k=16, SINGLE-term fp16 ----
        const uint32_t bth = vhB[s] + boffT4;
        #pragma unroll
        for (int j = 0; j < 16; j += 2) {
            uint32_t b0, b1, b2, b3;
            ldsm_x4t(b0, b1, b2, b3, bth + j * 16);
            mma_f16(cacc[j],     ph0, ph1, ph2, ph3, b0, b1);
            mma_f16(cacc[j + 1], ph0, ph1, ph2, ph3, b2, b3);
        }
    }

    // ---- per-warp (mx, rs) -> smem; merge frames across wc ----
    rs0 += __shfl_xor_sync(0xffffffffu, rs0, 1);
    rs0 += __shfl_xor_sync(0xffffffffu, rs0, 2);
    rs1 += __shfl_xor_sync(0xffffffffu, rs1, 1);
    rs1 += __shfl_xor_sync(0xffffffffu, rs1, 2);
    if (t == 0) {
        MXs[wc * 32 + rA] = mx0;  MXs[wc * 32 + rA + 8] = mx1;
        RSs[wc * 32 + rA] = rs0;  RSs[wc * 32 + rA + 8] = rs1;
    }
    __syncthreads();
    if (tid < 32) {
        float m0 = MXs[tid], m1 = MXs[32 + tid];
        float m2 = MXs[64 + tid], m3 = MXs[96 + tid];
        float M = fmaxf(fmaxf(m0, m1), fmaxf(m2, m3));
        float R = RSs[tid] * __expf(m0 - M) + RSs[32 + tid] * __expf(m1 - M) +
                  RSs[64 + tid] * __expf(m2 - M) + RSs[96 + tid] * __expf(m3 - M);
        MXR[tid] = M;
        INV[tid] = 1.0f / R;
    }
    __syncthreads();

    const float sc0 = __expf(mx0 - MXR[rA]);
    const float sc1 = __expf(mx1 - MXR[rA + 8]);

    // ---- parallel epilogue: each wc writes its own Jt region ----
    float* Jt = (float*)(sm + OFF_VH0) + wc * 4224;   // 32 x 132 f32 per region
    #pragma unroll
    for (int j = 0; j < 16; j++) {
        const int d0 = j * 8 + 2 * t;
        Jt[rA * 132 + d0]           = cacc[j][0] * sc0;
        Jt[rA * 132 + d0 + 1]       = cacc[j][1] * sc0;
        Jt[(rA + 8) * 132 + d0]     = cacc[j][2] * sc1;
        Jt[(rA + 8) * 132 + d0 + 1] = cacc[j][3] * sc1;
    }
    __syncthreads();

    // ---- n-reduce: sum over rows of (Uc + (sum_p ctx_p)*inv) ----
    {
        float* J0 = (float*)(sm + OFF_VH0);
        int h = tid >> 7, d = tid & 127;   // 2 groups x 16 rows
        float s = 0.0f;
        #pragma unroll
        for (int r = 0; r < 16; r++) {
            int row = h * 16 + r;
            float cv = J0[row * 132 + d] + J0[4224 + row * 132 + d] +
                       J0[8448 + row * 132 + d] + J0[12672 + row * 132 + d];
            uint32_t uh = UC32h[row * 68 + (d >> 1)];
            uint32_t ul = UC32l[row * 68 + (d >> 1)];
            float uc = (d & 1) ? (f16hi(uh) + f16hi(ul)) : (f16lo(uh) + f16lo(ul));
            s += uc + cv * INV[row];
        }
        RED[h * 128 + d] = s;
    }
    __syncthreads();
    if (tid < 128)
        part[(size_t)blockIdx.x * D_ + tid] = RED[tid] + RED[128 + tid];
}

// ============================================================================
__global__ __launch_bounds__(256)
void reduce_kernel(const float* __restrict__ part, const float* __restrict__ q,
                   float* __restrict__ out) {
    int i = blockIdx.x * blockDim.x + threadIdx.x;
    int b = i >> 7, d = i & 127;
    float s = 0.0f;
    #pragma unroll
    for (int nt = 0; nt < 16; nt++)
        s += part[(size_t)(b * 16 + nt) * D_ + d];
    out[i] = s * q[d] * (1.0f / (float)N_);
}

// ============================================================================
extern "C" void kernel_launch(void* const* d_in, const int* in_sizes, int n_in,
                              void* d_out, int out_size) {
    const float* h_c = (const float*)d_in[0];
    const float* h_p = (const float*)d_in[1];
    const float* U_w = (const float*)d_in[2];
    const float* U_b = (const float*)d_in[3];
    const float* V_w = (const float*)d_in[4];
    const float* V_b = (const float*)d_in[5];
    const float* q   = (const float*)d_in[6];
    float* out = (float*)d_out;

    void *pPart;
    cudaGetSymbolAddress(&pPart, g_part);

    cudaFuncSetAttribute(proj_kernel,
                         cudaFuncAttributeMaxDynamicSharedMemorySize, PROJ_SMEM);
    cudaFuncSetAttribute(attn_kernel,
                         cudaFuncAttributeMaxDynamicSharedMemorySize, ATTN_SMEM);

    convw_kernel<<<32, 256>>>(U_w, V_w);
    proj_kernel<<<768, 512, PROJ_SMEM>>>(h_c, h_p, U_b, V_b);
    attn_kernel<<<B_ * 16, 256, ATTN_SMEM>>>((float*)pPart);
    reduce_kernel<<<(B_ * D_) / 256, 256>>>((const float*)pPart, q, out);
}

// round 17
// speedup vs baseline: 1.3258x; 1.0204x over previous
#include <cuda_runtime.h>
#include <cuda_bf16.h>
#include <cstdint>

#define B_ 64
#define N_ 512
#define M_ 1024
#define D_ 128

typedef unsigned long long ull;

extern __shared__ char dynsm[];

// ---------------- device scratch (allocation-free) ----------------
__device__ __nv_bfloat16 g_UcHi[(size_t)B_ * N_ * D_];
__device__ __nv_bfloat16 g_UcLo[(size_t)B_ * N_ * D_];
__device__ __nv_bfloat16 g_VpHi[(size_t)B_ * M_ * D_];
__device__ __nv_bfloat16 g_VpLo[(size_t)B_ * M_ * D_];
__device__ uint32_t g_WuH[128 * 64], g_WuL[128 * 64];   // W as u32(bf16x2)
__device__ uint32_t g_WvH[128 * 64], g_WvL[128 * 64];
__device__ float g_part[(size_t)B_ * 16 * D_];

// ---------------- helpers ----------------
__device__ __forceinline__ uint32_t pack_bf16x2(float hi, float lo) {
    uint32_t r;
    asm("cvt.rn.bf16x2.f32 %0, %1, %2;" : "=r"(r) : "f"(hi), "f"(lo));
    return r;
}
__device__ __forceinline__ float lo_f(uint32_t p) { return __uint_as_float(p << 16); }
__device__ __forceinline__ float hi_f(uint32_t p) { return __uint_as_float(p & 0xffff0000u); }

__device__ __forceinline__ uint32_t pack_f16x2(float hi, float lo) {
    uint32_t r;
    asm("cvt.rn.f16x2.f32 %0, %1, %2;" : "=r"(r) : "f"(hi), "f"(lo));
    return r;
}
__device__ __forceinline__ float f16lo(uint32_t p) {
    float f;
    asm("{.reg .b16 l, h; mov.b32 {l, h}, %1; cvt.f32.f16 %0, l;}"
        : "=f"(f) : "r"(p));
    return f;
}
__device__ __forceinline__ float f16hi(uint32_t p) {
    float f;
    asm("{.reg .b16 l, h; mov.b32 {l, h}, %1; cvt.f32.f16 %0, h;}"
        : "=f"(f) : "r"(p));
    return f;
}
__device__ __forceinline__ uint32_t mul_f16x2(uint32_t a, uint32_t b) {
    uint32_t r;
    asm("mul.rn.f16x2 %0, %1, %2;" : "=r"(r) : "r"(a), "r"(b));
    return r;
}

__device__ __forceinline__ uint32_t smem_u32(const void* p) {
    uint32_t a;
    asm("{ .reg .u64 t; cvta.to.shared.u64 t, %1; cvt.u32.u64 %0, t; }"
        : "=r"(a) : "l"(p));
    return a;
}
__device__ __forceinline__ void mma_bf16(float* c, uint32_t a0, uint32_t a1,
                                         uint32_t a2, uint32_t a3,
                                         uint32_t b0, uint32_t b1) {
    asm volatile(
        "mma.sync.aligned.m16n8k16.row.col.f32.bf16.bf16.f32 "
        "{%0,%1,%2,%3},{%4,%5,%6,%7},{%8,%9},{%0,%1,%2,%3};"
        : "+f"(c[0]), "+f"(c[1]), "+f"(c[2]), "+f"(c[3])
        : "r"(a0), "r"(a1), "r"(a2), "r"(a3), "r"(b0), "r"(b1));
}
__device__ __forceinline__ void mma_f16(float* c, uint32_t a0, uint32_t a1,
                                        uint32_t a2, uint32_t a3,
                                        uint32_t b0, uint32_t b1) {
    asm volatile(
        "mma.sync.aligned.m16n8k16.row.col.f32.f16.f16.f32 "
        "{%0,%1,%2,%3},{%4,%5,%6,%7},{%8,%9},{%0,%1,%2,%3};"
        : "+f"(c[0]), "+f"(c[1]), "+f"(c[2]), "+f"(c[3])
        : "r"(a0), "r"(a1), "r"(a2), "r"(a3), "r"(b0), "r"(b1));
}
// fp16-accumulator variant (C as 2 packed f16x2 regs)
__device__ __forceinline__ void mma_f16c16(uint32_t& c0, uint32_t& c1,
                                           uint32_t a0, uint32_t a1,
                                           uint32_t a2, uint32_t a3,
                                           uint32_t b0, uint32_t b1) {
    asm volatile(
        "mma.sync.aligned.m16n8k16.row.col.f16.f16.f16.f16 "
        "{%0,%1},{%2,%3,%4,%5},{%6,%7},{%0,%1};"
        : "+r"(c0), "+r"(c1)
        : "r"(a0), "r"(a1), "r"(a2), "r"(a3), "r"(b0), "r"(b1));
}
__device__ __forceinline__ void ldsm_x4(uint32_t& r0, uint32_t& r1, uint32_t& r2,
                                        uint32_t& r3, uint32_t addr) {
    asm volatile("ldmatrix.sync.aligned.m8n8.x4.shared.b16 {%0,%1,%2,%3}, [%4];"
                 : "=r"(r0), "=r"(r1), "=r"(r2), "=r"(r3) : "r"(addr));
}
__device__ __forceinline__ void ldsm_x2(uint32_t& r0, uint32_t& r1, uint32_t addr) {
    asm volatile("ldmatrix.sync.aligned.m8n8.x2.shared.b16 {%0,%1}, [%2];"
                 : "=r"(r0), "=r"(r1) : "r"(addr));
}
__device__ __forceinline__ void ldsm_x4t(uint32_t& r0, uint32_t& r1, uint32_t& r2,
                                         uint32_t& r3, uint32_t addr) {
    asm volatile("ldmatrix.sync.aligned.m8n8.x4.trans.shared.b16 {%0,%1,%2,%3}, [%4];"
                 : "=r"(r0), "=r"(r1), "=r"(r2), "=r"(r3) : "r"(addr));
}
__device__ __forceinline__ void cpa16(uint32_t dst, const void* src) {
    asm volatile("cp.async.cg.shared.global [%0], [%1], 16;"
                 :: "r"(dst), "l"(src) : "memory");
}
#define CP_COMMIT() asm volatile("cp.async.commit_group;" ::: "memory")
#define CP_WAIT0() asm volatile("cp.async.wait_group 0;" ::: "memory")

// ============================================================================
// One-shot W conversion: fp32 -> bf16 hi/lo (for proj's internal bf16 MMA).
// ============================================================================
__global__ __launch_bounds__(256)
void convw_kernel(const float* __restrict__ Uw, const float* __restrict__ Vw) {
    int i = blockIdx.x * 256 + threadIdx.x;      // 0..8191
    int j = i & 4095;
    const float4* src = (i < 4096) ? (const float4*)Uw : (const float4*)Vw;
    uint32_t* dh = (i < 4096) ? g_WuH : g_WvH;
    uint32_t* dl = (i < 4096) ? g_WuL : g_WvL;
    float4 v = src[j];
    uint32_t h0 = pack_bf16x2(v.y, v.x);
    uint32_t l0 = pack_bf16x2(v.y - hi_f(h0), v.x - lo_f(h0));
    uint32_t h1 = pack_bf16x2(v.w, v.z);
    uint32_t l1 = pack_bf16x2(v.w - hi_f(h1), v.z - lo_f(h1));
    dh[j * 2] = h0; dh[j * 2 + 1] = h1;
    dl[j * 2] = l0; dl[j * 2 + 1] = l1;
}

// ============================================================================
// Merged projection via bf16 HMMA: relu(X @ W^T + b) -> fp16 hi/lo.
// 128-row CTAs: W staged ONCE, two 64-row X blocks processed in place.
// Grid 768: blocks [0,256) -> Uc from h_c, [256,768) -> Vp from h_p.
// ============================================================================
#define PJ_WH 0
#define PJ_WL 34816
#define PJ_XH 69632
#define PJ_XL 87040
#define PROJ_SMEM 104448

__global__ __launch_bounds__(512, 1)
void proj_kernel(const float* __restrict__ Xc, const float* __restrict__ Xp,
                 const float* __restrict__ Ubias, const float* __restrict__ Vbias) {
    char* sm = dynsm;
    const uint32_t smu = smem_u32(sm);
    const int tid = threadIdx.x, wid = tid >> 5, lane = tid & 31;
    const int wr = wid & 3, wc = wid >> 2;
    const int g = lane >> 2, t = lane & 3;
    const int blk = blockIdx.x;
    const bool isU = blk < 256;
    const float* X = isU ? Xc : Xp;
    const uint32_t* WHg = isU ? g_WuH : g_WvH;
    const uint32_t* WLg = isU ? g_WuL : g_WvL;
    const float* bias = isU ? Ubias : Vbias;
    uint32_t* oH = (uint32_t*)(isU ? g_UcHi : g_VpHi);
    uint32_t* oL = (uint32_t*)(isU ? g_UcLo : g_VpLo);
    const size_t row0 = (size_t)(isU ? blk : blk - 256) * 128;

    // stage W once
    uint4* WHs = (uint4*)(sm + PJ_WH);
    uint4* WLs = (uint4*)(sm + PJ_WL);
    const uint4* WHg4 = (const uint4*)WHg;
    const uint4* WLg4 = (const uint4*)WLg;
    #pragma unroll
    for (int it = 0; it < 4; it++) {
        int i = it * 512 + tid;
        int r = i >> 4, c = i & 15;
        WHs[r * 17 + c] = WHg4[i];
        WLs[r * 17 + c] = WLg4[i];
    }

    const int l7 = lane & 7, l8 = (lane >> 3) & 1, l16 = lane >> 4;
    const uint32_t aoffH = smu + PJ_XH + ((16 * wr + l7 + l8 * 8) * 68 + l16 * 4) * 4;
    const uint32_t aoffL = smu + PJ_XL + ((16 * wr + l7 + l8 * 8) * 68 + l16 * 4) * 4;
    const uint32_t boffH = smu + PJ_WH + ((wc * 32 + l7) * 68 + l8 * 4) * 4;
    const uint32_t boffL = smu + PJ_WL + ((wc * 32 + l7) * 68 + l8 * 4) * 4;
    const int rA = 16 * wr + g;
    const float2* b2 = (const float2*)bias;
    uint32_t* XH = (uint32_t*)(sm + PJ_XH);
    uint32_t* XL = (uint32_t*)(sm + PJ_XL);

    #pragma unroll
    for (int rb = 0; rb < 2; rb++) {
        // stage X block (64 x 128)
        const float4* Xg = (const float4*)(X + (row0 + rb * 64) * D_);
        #pragma unroll
        for (int it = 0; it < 4; it++) {
            int i = it * 512 + tid;
            int r = i >> 5, c4 = i & 31;
            float4 v = Xg[i];
            uint32_t h0 = pack_bf16x2(v.y, v.x);
            uint32_t l0 = pack_bf16x2(v.y - hi_f(h0), v.x - lo_f(h0));
            uint32_t h1 = pack_bf16x2(v.w, v.z);
            uint32_t l1 = pack_bf16x2(v.w - hi_f(h1), v.z - lo_f(h1));
            XH[r * 68 + c4 * 2] = h0; XH[r * 68 + c4 * 2 + 1] = h1;
            XL[r * 68 + c4 * 2] = l0; XL[r * 68 + c4 * 2 + 1] = l1;
        }
        __syncthreads();

        float accA[4][4], accB[4][4];
        #pragma unroll
        for (int j = 0; j < 4; j++)
            #pragma unroll
            for (int q = 0; q < 4; q++) { accA[j][q] = 0.0f; accB[j][q] = 0.0f; }

        #pragma unroll
        for (int kk = 0; kk < 8; kk++) {
            uint32_t ah0, ah1, ah2, ah3, al0, al1, al2, al3;
            ldsm_x4(ah0, ah1, ah2, ah3, aoffH + kk * 32);
            ldsm_x4(al0, al1, al2, al3, aoffL + kk * 32);
            #pragma unroll
            for (int j = 0; j < 4; j++) {
                uint32_t bh0, bh1, bl0, bl1;
                ldsm_x2(bh0, bh1, boffH + j * 2176 + kk * 32);
                ldsm_x2(bl0, bl1, boffL + j * 2176 + kk * 32);
                mma_bf16(accA[j], ah0, ah1, ah2, ah3, bh0, bh1);
                mma_bf16(accB[j], ah0, ah1, ah2, ah3, bl0, bl1);
                mma_bf16(accB[j], al0, al1, al2, al3, bh0, bh1);
            }
        }

        // epilogue: bias + relu + fp16 hi/lo split (regs only)
        const size_t rbase = row0 + rb * 64;
        #pragma unroll
        for (int j = 0; j < 4; j++) {
            const int cpair = wc * 16 + j * 4 + t;
            float2 bb = b2[cpair];
            float o0 = fmaxf(accA[j][0] + accB[j][0] + bb.x, 0.0f);
            float o1 = fmaxf(accA[j][1] + accB[j][1] + bb.y, 0.0f);
            uint32_t h = pack_f16x2(o1, o0);
            uint32_t l = pack_f16x2(o1 - f16hi(h), o0 - f16lo(h));
            oH[(rbase + rA) * 64 + cpair] = h;
            oL[(rbase + rA) * 64 + cpair] = l;
            float o2 = fmaxf(accA[j][2] + accB[j][2] + bb.x, 0.0f);
            float o3 = fmaxf(accA[j][3] + accB[j][3] + bb.y, 0.0f);
            uint32_t h2 = pack_f16x2(o3, o2);
            uint32_t l2 = pack_f16x2(o3 - f16hi(h2), o2 - f16lo(h2));
            oH[(rbase + rA + 8) * 64 + cpair] = h2;
            oL[(rbase + rA + 8) * 64 + cpair] = l2;
        }
        __syncthreads();
    }
}

// ============================================================================
// Fused attention: fp16, online max (lazy rescale), fp16 cross + ctx
// accumulators, HOISTED A_hi fragments (Uc invariant across chunks).
// CTA = (b, 32-row n-tile), grid 1024, 256 thr, 2 CTAs/SM.
// ============================================================================
#define OFF_UCH 0
#define OFF_UCL 8704
#define OFF_VH0 17408
#define OFF_VL0 34816
#define OFF_VH1 52224
#define OFF_VL1 69632
#define OFF_MX  87040
#define OFF_RSS 87552
#define OFF_MXR 88064
#define OFF_INV 88192
#define OFF_RED 88320
#define ATTN_SMEM 89344

__global__ __launch_bounds__(256, 2)
void attn_kernel(float* __restrict__ part) {
    char* sm = dynsm;
    const uint32_t smu = smem_u32(sm);
    const int tid = threadIdx.x, wid = tid >> 5, lane = tid & 31;
    const int wr = wid & 1, wc = wid >> 1;          // 2 x 4 warp grid
    const int g = lane >> 2, t = lane & 3;
    const int b = blockIdx.x >> 4, nt = blockIdx.x & 15;

    uint32_t* UC32h = (uint32_t*)(sm + OFF_UCH);   // 32 rows, stride 68 u32
    uint32_t* UC32l = (uint32_t*)(sm + OFF_UCL);
    float* MXs = (float*)(sm + OFF_MX);
    float* RSs = (float*)(sm + OFF_RSS);
    float* MXR = (float*)(sm + OFF_MXR);
    float* INV = (float*)(sm + OFF_INV);
    float* RED = (float*)(sm + OFF_RED);

    const uint4* ucHg = (const uint4*)(g_UcHi + ((size_t)(b * N_ + nt * 32)) * D_);
    const uint4* ucLg = (const uint4*)(g_UcLo + ((size_t)(b * N_ + nt * 32)) * D_);
    const uint4* vpHg = (const uint4*)(g_VpHi + (size_t)b * M_ * D_);
    const uint4* vpLg = (const uint4*)(g_VpLo + (size_t)b * M_ * D_);

    const uint32_t vhB[2] = {smu + OFF_VH0, smu + OFF_VH1};
    const uint32_t vlB[2] = {smu + OFF_VL0, smu + OFF_VL1};

    const int l7 = lane & 7, l8 = (lane >> 3) & 1, l16 = lane >> 4;
    const uint32_t aoffH = smu + OFF_UCH + ((16 * wr + l7 + l8 * 8) * 68 + l16 * 4) * 4;
    const uint32_t aoffL = smu + OFF_UCL + ((16 * wr + l7 + l8 * 8) * 68 + l16 * 4) * 4;
    const uint32_t boffV4 = ((wc * 16 + l16 * 8 + l7) * 68 + l8 * 4) * 4;
    const uint32_t boffT4 = ((wc * 16 + l8 * 8 + l7) * 68) * 4 + l16 * 16;

    // hoisted cp.async per-thread addressing (i = it*256+tid)
    const uint32_t cpdst = ((tid >> 4) * 68 + (tid & 15) * 4) * 4;  // + it*4352
    const int cpsrc = tid;                                           // + it*256

    const int rA = 16 * wr + g;
    uint32_t cacc[16][2];            // fp16 packed ctx accumulators
    #pragma unroll
    for (int j = 0; j < 16; j++) { cacc[j][0] = 0u; cacc[j][1] = 0u; }
    float rs0 = 0.0f, rs1 = 0.0f;
    float mx0 = 0.0f, mx1 = 0.0f;     // scores >= 0 (ReLU operands)
    uint32_t AH[8][4];                // hoisted A_hi frags (Uc, all 8 k-steps)

    // stage Uc (cp.async) + chunk 0 V, single commit
    #pragma unroll
    for (int it = 0; it < 2; it++) {
        cpa16(smu + OFF_UCH + cpdst + it * 4352, ucHg + cpsrc + it * 256);
        cpa16(smu + OFF_UCL + cpdst + it * 4352, ucLg + cpsrc + it * 256);
    }
    #pragma unroll
    for (int it = 0; it < 4; it++) {
        cpa16(vhB[0] + cpdst + it * 4352, vpHg + cpsrc + it * 256);
        cpa16(vlB[0] + cpdst + it * 4352, vpLg + cpsrc + it * 256);
    }
    CP_COMMIT();

    for (int mc = 0; mc < 16; mc++) {
        const int s = mc & 1;
        CP_WAIT0();
        __syncthreads();
        if (mc == 0) {   // hoist A_hi fragments once (Uc now resident)
            #pragma unroll
            for (int kk = 0; kk < 8; kk++)
                ldsm_x4(AH[kk][0], AH[kk][1], AH[kk][2], AH[kk][3],
                        aoffH + kk * 32);
        }
        if (mc + 1 < 16) {
            const int s2 = s ^ 1;
            const int srcb = cpsrc + (mc + 1) * 1024;
            #pragma unroll
            for (int it = 0; it < 4; it++) {
                cpa16(vhB[s2] + cpdst + it * 4352, vpHg + srcb + it * 256);
                cpa16(vlB[s2] + cpdst + it * 4352, vpLg + srcb + it * 256);
            }
            CP_COMMIT();
        }

        // ---- scores: 16n x 16m (own m-slice), k=128, fp16 3-term ----
        float accA[2][4];
        uint32_t accB[2][2];
        #pragma unroll
        for (int j = 0; j < 2; j++) {
            #pragma unroll
            for (int q = 0; q < 4; q++) accA[j][q] = 0.0f;
            accB[j][0] = 0u; accB[j][1] = 0u;
        }

        const uint32_t bvh = vhB[s] + boffV4, bvl = vlB[s] + boffV4;
        #pragma unroll
        for (int kk = 0; kk < 8; kk++) {
            uint32_t al0, al1, al2, al3;
            ldsm_x4(al0, al1, al2, al3, aoffL + kk * 32);
            uint32_t bh0, bh1, bh2, bh3, bl0, bl1, bl2, bl3;
            ldsm_x4(bh0, bh1, bh2, bh3, bvh + kk * 32);
            ldsm_x4(bl0, bl1, bl2, bl3, bvl + kk * 32);
            mma_f16(accA[0], AH[kk][0], AH[kk][1], AH[kk][2], AH[kk][3], bh0, bh1);
            mma_f16c16(accB[0][0], accB[0][1],
                       AH[kk][0], AH[kk][1], AH[kk][2], AH[kk][3], bl0, bl1);
            mma_f16c16(accB[0][0], accB[0][1], al0, al1, al2, al3, bh0, bh1);
            mma_f16(accA[1], AH[kk][0], AH[kk][1], AH[kk][2], AH[kk][3], bh2, bh3);
            mma_f16c16(accB[1][0], accB[1][1],
                       AH[kk][0], AH[kk][1], AH[kk][2], AH[kk][3], bl2, bl3);
            mma_f16c16(accB[1][0], accB[1][1], al0, al1, al2, al3, bh2, bh3);
        }

        // ---- per-warp online max (lazy rescale) + exp + fp16 P pack ----
        float s00 = accA[0][0] + f16lo(accB[0][0]);
        float s01 = accA[0][1] + f16hi(accB[0][0]);
        float s02 = accA[0][2] + f16lo(accB[0][1]);
        float s03 = accA[0][3] + f16hi(accB[0][1]);
        float s10 = accA[1][0] + f16lo(accB[1][0]);
        float s11 = accA[1][1] + f16hi(accB[1][0]);
        float s12 = accA[1][2] + f16lo(accB[1][1]);
        float s13 = accA[1][3] + f16hi(accB[1][1]);
        float c0 = fmaxf(fmaxf(s00, s01), fmaxf(s10, s11));
        float c1 = fmaxf(fmaxf(s02, s03), fmaxf(s12, s13));
        c0 = fmaxf(c0, __shfl_xor_sync(0xffffffffu, c0, 1));
        c0 = fmaxf(c0, __shfl_xor_sync(0xffffffffu, c0, 2));
        c1 = fmaxf(c1, __shfl_xor_sync(0xffffffffu, c1, 1));
        c1 = fmaxf(c1, __shfl_xor_sync(0xffffffffu, c1, 2));
        if (c0 > mx0 || c1 > mx1) {   // warp-uniform branch
            float nm0 = fmaxf(mx0, c0), nm1 = fmaxf(mx1, c1);
            float scl0 = __expf(mx0 - nm0), scl1 = __expf(mx1 - nm1);
            rs0 *= scl0; rs1 *= scl1;
            uint32_t sl0 = pack_f16x2(scl0, scl0);
            uint32_t sl1 = pack_f16x2(scl1, scl1);
            #pragma unroll
            for (int j = 0; j < 16; j++) {
                cacc[j][0] = mul_f16x2(cacc[j][0], sl0);
                cacc[j][1] = mul_f16x2(cacc[j][1], sl1);
            }
            mx0 = nm0; mx1 = nm1;
        }
        float e0 = __expf(s00 - mx0), e1 = __expf(s01 - mx0);
        float f0 = __expf(s10 - mx0), f1 = __expf(s11 - mx0);
        float e2 = __expf(s02 - mx1), e3 = __expf(s03 - mx1);
        float f2 = __expf(s12 - mx1), f3 = __expf(s13 - mx1);
        rs0 += e0 + e1 + f0 + f1;
        rs1 += e2 + e3 + f2 + f3;
        uint32_t ph0 = pack_f16x2(e1, e0);
        uint32_t ph1 = pack_f16x2(e3, e2);
        uint32_t ph2 = pack_f16x2(f1, f0);
        uint32_t ph3 = pack_f16x2(f3, f2);

        // ---- ctx partial: 16n x 128d, k=16, single-term fp16, fp16 accum ----
        const uint32_t bth = vhB[s] + boffT4;
        #pragma unroll
        for (int j = 0; j < 16; j += 2) {
            uint32_t b0, b1, b2, b3;
            ldsm_x4t(b0, b1, b2, b3, bth + j * 16);
            mma_f16c16(cacc[j][0],     cacc[j][1],     ph0, ph1, ph2, ph3, b0, b1);
            mma_f16c16(cacc[j + 1][0], cacc[j + 1][1], ph0, ph1, ph2, ph3, b2, b3);
        }
    }

    // ---- per-warp (mx, rs) -> smem; merge frames across wc ----
    rs0 += __shfl_xor_sync(0xffffffffu, rs0, 1);
    rs0 += __shfl_xor_sync(0xffffffffu, rs0, 2);
    rs1 += __shfl_xor_sync(0xffffffffu, rs1, 1);
    rs1 += __shfl_xor_sync(0xffffffffu, rs1, 2);
    if (t == 0) {
        MXs[wc * 32 + rA] = mx0;  MXs[wc * 32 + rA + 8] = mx1;
        RSs[wc * 32 + rA] = rs0;  RSs[wc * 32 + rA + 8] = rs1;
    }
    __syncthreads();
    if (tid < 32) {
        float m0 = MXs[tid], m1 = MXs[32 + tid];
        float m2 = MXs[64 + tid], m3 = MXs[96 + tid];
        float M = fmaxf(fmaxf(m0, m1), fmaxf(m2, m3));
        float R = RSs[tid] * __expf(m0 - M) + RSs[32 + tid] * __expf(m1 - M) +
                  RSs[64 + tid] * __expf(m2 - M) + RSs[96 + tid] * __expf(m3 - M);
        MXR[tid] = M;
        INV[tid] = 1.0f / R;
    }
    __syncthreads();

    const float sc0 = __expf(mx0 - MXR[rA]);
    const float sc1 = __expf(mx1 - MXR[rA + 8]);

    // ---- parallel epilogue: each wc writes its own Jt region ----
    float* Jt = (float*)(sm + OFF_VH0) + wc * 4224;   // 32 x 132 f32 per region
    #pragma unroll
    for (int j = 0; j < 16; j++) {
        const int d0 = j * 8 + 2 * t;
        Jt[rA * 132 + d0]           = f16lo(cacc[j][0]) * sc0;
        Jt[rA * 132 + d0 + 1]       = f16hi(cacc[j][0]) * sc0;
        Jt[(rA + 8) * 132 + d0]     = f16lo(cacc[j][1]) * sc1;
        Jt[(rA + 8) * 132 + d0 + 1] = f16hi(cacc[j][1]) * sc1;
    }
    __syncthreads();

    // ---- n-reduce: sum over rows of (Uc + (sum_p ctx_p)*inv) ----
    {
        float* J0 = (float*)(sm + OFF_VH0);
        int h = tid >> 7, d = tid & 127;   // 2 groups x 16 rows
        float s = 0.0f;
        #pragma unroll
        for (int r = 0; r < 16; r++) {
            int row = h * 16 + r;
            float cv = J0[row * 132 + d] + J0[4224 + row * 132 + d] +
                       J0[8448 + row * 132 + d] + J0[12672 + row * 132 + d];
            uint32_t uh = UC32h[row * 68 + (d >> 1)];
            uint32_t ul = UC32l[row * 68 + (d >> 1)];
            float uc = (d & 1) ? (f16hi(uh) + f16hi(ul)) : (f16lo(uh) + f16lo(ul));
            s += uc + cv * INV[row];
        }
        RED[h * 128 + d] = s;
    }
    __syncthreads();
    if (tid < 128)
        part[(size_t)blockIdx.x * D_ + tid] = RED[tid] + RED[128 + tid];
}

// ============================================================================
__global__ __launch_bounds__(256)
void reduce_kernel(const float* __restrict__ part, const float* __restrict__ q,
                   float* __restrict__ out) {
    int i = blockIdx.x * blockDim.x + threadIdx.x;
    int b = i >> 7, d = i & 127;
    float s = 0.0f;
    #pragma unroll
    for (int nt = 0; nt < 16; nt++)
        s += part[(size_t)(b * 16 + nt) * D_ + d];
    out[i] = s * q[d] * (1.0f / (float)N_);
}

// ============================================================================
extern "C" void kernel_launch(void* const* d_in, const int* in_sizes, int n_in,
                              void* d_out, int out_size) {
    const float* h_c = (const float*)d_in[0];
    const float* h_p = (const float*)d_in[1];
    const float* U_w = (const float*)d_in[2];
    const float* U_b = (const float*)d_in[3];
    const float* V_w = (const float*)d_in[4];
    const float* V_b = (const float*)d_in[5];
    const float* q   = (const float*)d_in[6];
    float* out = (float*)d_out;

    void *pPart;
    cudaGetSymbolAddress(&pPart, g_part);

    cudaFuncSetAttribute(proj_kernel,
                         cudaFuncAttributeMaxDynamicSharedMemorySize, PROJ_SMEM);
    cudaFuncSetAttribute(attn_kernel,
                         cudaFuncAttributeMaxDynamicSharedMemorySize, ATTN_SMEM);

    convw_kernel<<<32, 256>>>(U_w, V_w);
    proj_kernel<<<768, 512, PROJ_SMEM>>>(h_c, h_p, U_b, V_b);
    attn_kernel<<<B_ * 16, 256, ATTN_SMEM>>>((float*)pPart);
    reduce_kernel<<<(B_ * D_) / 256, 256>>>((const float*)pPart, q, out);
}